// round 10
// baseline (speedup 1.0000x reference)
#include <cuda_runtime.h>
#include <cstdint>
#include <math.h>

#define BB 4
#define HH 8
#define SS 2048
#define DM 768
#define DH 96
#define ROWS (BB*SS)          // 8192
#define GK DM                 // 768

// ---------------- scratch (device globals; no allocation allowed) ----------
__device__ float g_Q[(size_t)BB*HH*SS*DH];
__device__ float g_K[(size_t)BB*HH*SS*DH];
__device__ float g_V[(size_t)BB*HH*SS*DH];
__device__ float g_ctx[(size_t)ROWS*DM];
__device__ float g_Wt[(size_t)4*DM*DM];            // transposed+rounded weights
__device__ float g_attn_fb[(size_t)BB*HH*SS*SS];   // fallback if attn not in d_out
__device__ float g_out_fb[(size_t)ROWS*DM];        // fallback if out not in d_out

// ---------------- helpers ---------------------------------------------------
__device__ __forceinline__ uint32_t smem_u32(const void* p) {
    uint32_t a;
    asm("{ .reg .u64 t; cvta.to.shared.u64 t, %1; cvt.u32.u64 %0, t; }" : "=r"(a) : "l"(p));
    return a;
}
__device__ __forceinline__ float tf32r(float x) {
    uint32_t u;
    asm("cvt.rna.tf32.f32 %0, %1;" : "=r"(u) : "f"(x));
    return __uint_as_float(u);
}
__device__ __forceinline__ void cp16(uint32_t dst, const void* src) {
    asm volatile("cp.async.cg.shared.global [%0], [%1], 16;" :: "r"(dst), "l"(src));
}

// mma.sync m16n8k8 tf32 (baseline PTX, works on compute_103)
#define MMA4(c, a, b0, b1) \
    asm volatile("mma.sync.aligned.m16n8k8.row.col.f32.tf32.tf32.f32 " \
        "{%0,%1,%2,%3},{%4,%5,%6,%7},{%8,%9},{%0,%1,%2,%3};" \
        : "+f"((c)[0]), "+f"((c)[1]), "+f"((c)[2]), "+f"((c)[3]) \
        : "r"((a)[0]), "r"((a)[1]), "r"((a)[2]), "r"((a)[3]), "r"(b0), "r"(b1))

// FMA-pipe exp (avoids MUFU bottleneck). Inputs are O(1) or ~-1e9 (masked).
__device__ __forceinline__ float fexp(float x) {
    float y = x * 1.442695040888963f;
    y = fmaxf(y, -126.0f);
    float t = y + 12582912.0f;          // round-to-nearest-even
    float n = t - 12582912.0f;
    float f = y - n;
    float p = 1.33335581e-3f;
    p = fmaf(p, f, 9.61812911e-3f);
    p = fmaf(p, f, 5.55041087e-2f);
    p = fmaf(p, f, 2.40226507e-1f);
    p = fmaf(p, f, 6.93147180e-1f);
    p = fmaf(p, f, 1.0f);
    float s = __int_as_float(((int)n + 127) << 23);
    return p * s;
}

// ---------------- weight transpose + tf32 round (all 4 weights, 1 launch) ---
__global__ __launch_bounds__(256) void wt4_kernel(
    const float* __restrict__ w0, const float* __restrict__ w1,
    const float* __restrict__ w2, const float* __restrict__ w3,
    float* __restrict__ Wt)
{
    __shared__ float t[32][33];
    int z = blockIdx.z;
    const float* W = (z == 0) ? w0 : (z == 1) ? w1 : (z == 2) ? w2 : w3;
    float* out = Wt + (size_t)z * DM * DM;
    int tx = threadIdx.x, ty = threadIdx.y;             // 32 x 8
    int bx = blockIdx.x * 32, by = blockIdx.y * 32;
#pragma unroll
    for (int j = 0; j < 32; j += 8)
        t[ty + j][tx] = W[(size_t)(by + ty + j) * DM + bx + tx];
    __syncthreads();
#pragma unroll
    for (int j = 0; j < 32; j += 8)
        out[(size_t)(bx + ty + j) * DM + by + tx] = tf32r(t[tx][ty + j]);
}

// ---------------- projection GEMM via mma.sync tf32 --------------------------
// C[8192,768] = X[8192,768] @ Wt[768,768]^T + bias. Tile 128x128, K-chunk 16,
// 3-stage cp.async pipeline (dynamic smem). A-frags tf32-rounded in registers.
#define PJM 128
#define PJN 128
#define PJK 16
#define ASD 20
#define STG 2560              // floats per stage per matrix (128*20)
#define NST 3
#define NCHK (GK / PJK)       // 48
#define PROJ_SMEM (NST * STG * 2 * 4)   // 61440 B

__device__ __forceinline__ void proj_load(
    int tid, int bm, int bn, int c, const float* X, const float* Wt,
    uint32_t abase, uint32_t bbase)
{
    int s = c % NST;
    uint32_t ab = abase + s * STG * 4;
    uint32_t bb = bbase + s * STG * 4;
    int k0 = c * PJK;
#pragma unroll
    for (int j = 0; j < 2; j++) {
        int i = tid + j * 256;
        int r = i >> 2, c4 = (i & 3) * 4;
        cp16(ab + (uint32_t)(r * ASD + c4) * 4, X + (size_t)(bm + r) * GK + k0 + c4);
    }
#pragma unroll
    for (int j = 0; j < 2; j++) {
        int i = tid + j * 256;
        int r = i >> 2, c4 = (i & 3) * 4;
        cp16(bb + (uint32_t)(r * ASD + c4) * 4, Wt + (size_t)(bn + r) * GK + k0 + c4);
    }
    asm volatile("cp.async.commit_group;" ::: "memory");
}

__device__ __forceinline__ void proj_body(
    const float* __restrict__ X, const float* __restrict__ Wt,
    const float* __restrict__ bias, float* __restrict__ out, int split)
{
    extern __shared__ float psm[];
    float* As = psm;                 // NST stages x 2560
    float* Bs = psm + NST * STG;
    const int tid = threadIdx.x, warp = tid >> 5, lane = tid & 31;
    const int g = lane >> 2, t = lane & 3;
    const int bm = blockIdx.y * PJM, bn = blockIdx.x * PJN;
    const int m0 = (warp & 3) * 32, n0 = (warp >> 2) * 64;

    uint32_t abase = smem_u32(As), bbase = smem_u32(Bs);

    float cf[2][8][4];
#pragma unroll
    for (int mt = 0; mt < 2; mt++)
#pragma unroll
        for (int nt = 0; nt < 8; nt++)
#pragma unroll
            for (int i = 0; i < 4; i++) cf[mt][nt][i] = 0.f;

    proj_load(tid, bm, bn, 0, X, Wt, abase, bbase);
    proj_load(tid, bm, bn, 1, X, Wt, abase, bbase);

    for (int c = 0; c < NCHK; c++) {
        if (c + 2 < NCHK) {
            proj_load(tid, bm, bn, c + 2, X, Wt, abase, bbase);
            asm volatile("cp.async.wait_group 2;" ::: "memory");
        } else if (c + 1 < NCHK) {
            asm volatile("cp.async.wait_group 1;" ::: "memory");
        } else {
            asm volatile("cp.async.wait_group 0;" ::: "memory");
        }
        __syncthreads();
        int s = c % NST;
        const float* Ab2 = As + s * STG;
        const float* Bb2 = Bs + s * STG;
#pragma unroll
        for (int kk = 0; kk < PJK; kk += 8) {
            uint32_t a[2][4];
#pragma unroll
            for (int mt = 0; mt < 2; mt++) {
                const float* ap = &Ab2[(m0 + mt * 16 + g) * ASD + kk + t];
                a[mt][0] = __float_as_uint(tf32r(ap[0]));
                a[mt][1] = __float_as_uint(tf32r(ap[8 * ASD]));
                a[mt][2] = __float_as_uint(tf32r(ap[4]));
                a[mt][3] = __float_as_uint(tf32r(ap[8 * ASD + 4]));
            }
            uint32_t bf[8][2];
#pragma unroll
            for (int nt = 0; nt < 8; nt++) {
                const float* bp = &Bb2[(n0 + nt * 8 + g) * ASD + kk + t];
                bf[nt][0] = __float_as_uint(bp[0]);
                bf[nt][1] = __float_as_uint(bp[4]);
            }
#pragma unroll
            for (int mt = 0; mt < 2; mt++)
#pragma unroll
                for (int nt = 0; nt < 8; nt++)
                    MMA4(cf[mt][nt], a[mt], bf[nt][0], bf[nt][1]);
        }
        __syncthreads();
    }

    // epilogue
#pragma unroll
    for (int mt = 0; mt < 2; mt++)
#pragma unroll
        for (int nt = 0; nt < 8; nt++) {
            int col = bn + n0 + nt * 8 + 2 * t;
            float b0v = __ldg(bias + col), b1v = __ldg(bias + col + 1);
#pragma unroll
            for (int hf = 0; hf < 2; hf++) {
                int m = bm + m0 + mt * 16 + hf * 8 + g;
                float v0 = cf[mt][nt][hf * 2] + b0v;
                float v1 = cf[mt][nt][hf * 2 + 1] + b1v;
                if (split) {
                    int bdx = m >> 11, sidx = m & (SS - 1);
                    int hh = col / DH, dd = col - hh * DH;
                    *(float2*)(out + (((size_t)bdx * HH + hh) * SS + sidx) * DH + dd) =
                        make_float2(tf32r(v0), tf32r(v1));
                } else {
                    *(float2*)(out + (size_t)m * DM + col) = make_float2(v0, v1);
                }
            }
        }
}

__global__ __launch_bounds__(256) void proj_qkv(
    const float* __restrict__ q_in, const float* __restrict__ k_in,
    const float* __restrict__ v_in,
    const float* __restrict__ bq, const float* __restrict__ bk,
    const float* __restrict__ bv,
    const float* __restrict__ Wt,
    float* __restrict__ outQ, float* __restrict__ outK, float* __restrict__ outV)
{
    int z = blockIdx.z;
    const float* X = (z == 0) ? q_in : (z == 1) ? k_in : v_in;
    const float* bias = (z == 0) ? bq : (z == 1) ? bk : bv;
    float* out = (z == 0) ? outQ : (z == 1) ? outK : outV;
    proj_body(X, Wt + (size_t)z * DM * DM, bias, out, 1);
}

__global__ __launch_bounds__(256) void proj_out(
    const float* __restrict__ X, const float* __restrict__ Wt,
    const float* __restrict__ bias, float* __restrict__ out)
{
    proj_body(X, Wt, bias, out, 0);
}

// ---------------- attention (QT=64, permuted Q/K frag layouts) --------------
#define QT 64
#define TK 128
#define NCH (SS / TK)     // 16
#define KVB 104           // V-pass stride (conflict-free k-indexed frags)
#define PED 132
#define QP_F 6144         // 64x96 permuted
#define KV_F 13312        // max(K permuted 12288, V 128x104)
#define PE_F (64*PED)     // 8448
#define ATTN_SMEM ((QP_F + KV_F + PE_F + 128 + 256 + 64) * 4)   // 113408

__global__ __launch_bounds__(256, 2) void attn_kernel(
    const float* __restrict__ gQ, const float* __restrict__ gK,
    const float* __restrict__ gV, const float* __restrict__ mask,
    float* __restrict__ attn, float* __restrict__ ctx)
{
    extern __shared__ float sm[];
    float* QP   = sm;                      // permuted Q frags
    float* KV   = sm + QP_F;               // K-permuted (pass A) / V (pass B)
    float* KP0  = KV;                      // 6144 (nt 0,1)
    float* KP1  = KV + 6144;               // 6144 (nt 2,3)
    float* pe   = sm + QP_F + KV_F;        // [64][132]
    float* ms   = pe + PE_F;               // [128]
    float* red  = ms + 128;                // [4][64]
    float* invs = red + 256;               // [64]

    const int tid = threadIdx.x;
    const int warp = tid >> 5, lane = tid & 31;
    const int g = lane >> 2, t = lane & 3;
    const int wm = warp & 1, wn = warp >> 1;          // 2(m) x 4(n)
    const int qt = blockIdx.x, h = blockIdx.y, b = blockIdx.z;

    const float* Qb = gQ + (((size_t)b * HH + h) * SS + (size_t)qt * QT) * DH;
    const float* Kb = gK + ((size_t)b * HH + h) * SS * DH;
    const float* Vb = gV + ((size_t)b * HH + h) * SS * DH;
    float* Ab = attn + (((size_t)b * HH + h) * SS + (size_t)qt * QT) * (size_t)SS;

    const uint32_t kvb = smem_u32(KV);

    // ---- Q permute fill (once): QP[A=((wm*2+mt)*12+kki)][lane][4] ----
    // j0=Q[r][k], j1=Q[r+8][k], j2=Q[r][k+4], j3=Q[r+8][k+4]
#pragma unroll
    for (int l = 0; l < 6; l++) {
        int gi = tid + l * 256;
        int Aq = gi >> 5, ln = gi & 31;
        int wmmt = Aq / 12, kki = Aq - wmmt * 12;
        int row = (wmmt >> 1) * 32 + (wmmt & 1) * 16 + (ln >> 2);
        int col = kki * 8 + (ln & 3);
        const float* qp = Qb + row * DH + col;
        float4 v;
        v.x = qp[0]; v.y = qp[8 * DH]; v.z = qp[4]; v.w = qp[8 * DH + 4];
        *(float4*)&QP[Aq * 128 + ln * 4] = v;
    }

    const float SCALE = rsqrtf((float)DH);
    float sumr[4] = {0.f, 0.f, 0.f, 0.f};

    // --- Pass A: logits -> exp -> gmem, row sums ---
    for (int c = 0; c < NCH; c++) {
        __syncthreads();
        const float* Kc = Kb + (size_t)c * TK * DH;
        // K permute fill: KP0 rows wn*32+{0..15}, KP1 rows wn*32+{16..31}
        // j0=K[r][k], j1=K[r][k+4], j2=K[r+8][k], j3=K[r+8][k+4]
#pragma unroll
        for (int l = 0; l < 12; l++) {
            int gi = tid + ((l >= 6) ? (l - 6) : l) * 256;
            int Ak = gi >> 5, ln = gi & 31;
            int wnn = Ak / 12, kki = Ak - wnn * 12;
            int row = wnn * 32 + ((l >= 6) ? 16 : 0) + (ln >> 2);
            int col = kki * 8 + (ln & 3);
            const float* kp = Kc + row * DH + col;
            float4 v;
            v.x = kp[0]; v.y = kp[4]; v.z = kp[8 * DH]; v.w = kp[8 * DH + 4];
            float* dst = (l >= 6) ? KP1 : KP0;
            *(float4*)&dst[Ak * 128 + ln * 4] = v;
        }
        if (tid < TK) ms[tid] = mask[(size_t)b * SS + c * TK + tid] * -1e9f;
        __syncthreads();

        float cf[2][4][4];
#pragma unroll
        for (int mt = 0; mt < 2; mt++)
#pragma unroll
            for (int nt = 0; nt < 4; nt++)
#pragma unroll
                for (int i = 0; i < 4; i++) cf[mt][nt][i] = 0.f;

#pragma unroll
        for (int kki = 0; kki < 12; kki++) {
            float4 q0 = *(float4*)&QP[((wm * 2 + 0) * 12 + kki) * 128 + lane * 4];
            float4 q1 = *(float4*)&QP[((wm * 2 + 1) * 12 + kki) * 128 + lane * 4];
            float4 k0 = *(float4*)&KP0[(wn * 12 + kki) * 128 + lane * 4];
            float4 k1 = *(float4*)&KP1[(wn * 12 + kki) * 128 + lane * 4];
            uint32_t a0[4] = {__float_as_uint(q0.x), __float_as_uint(q0.y),
                              __float_as_uint(q0.z), __float_as_uint(q0.w)};
            uint32_t a1[4] = {__float_as_uint(q1.x), __float_as_uint(q1.y),
                              __float_as_uint(q1.z), __float_as_uint(q1.w)};
            MMA4(cf[0][0], a0, __float_as_uint(k0.x), __float_as_uint(k0.y));
            MMA4(cf[0][1], a0, __float_as_uint(k0.z), __float_as_uint(k0.w));
            MMA4(cf[0][2], a0, __float_as_uint(k1.x), __float_as_uint(k1.y));
            MMA4(cf[0][3], a0, __float_as_uint(k1.z), __float_as_uint(k1.w));
            MMA4(cf[1][0], a1, __float_as_uint(k0.x), __float_as_uint(k0.y));
            MMA4(cf[1][1], a1, __float_as_uint(k0.z), __float_as_uint(k0.w));
            MMA4(cf[1][2], a1, __float_as_uint(k1.x), __float_as_uint(k1.y));
            MMA4(cf[1][3], a1, __float_as_uint(k1.z), __float_as_uint(k1.w));
        }

#pragma unroll
        for (int mt = 0; mt < 2; mt++)
#pragma unroll
            for (int nt = 0; nt < 4; nt++) {
                int lc = wn * 32 + nt * 8 + 2 * t;
                float m0 = ms[lc], m1 = ms[lc + 1];
                int gc = c * TK + lc;
                float e00 = fexp(cf[mt][nt][0] * SCALE + m0);
                float e01 = fexp(cf[mt][nt][1] * SCALE + m1);
                float e10 = fexp(cf[mt][nt][2] * SCALE + m0);
                float e11 = fexp(cf[mt][nt][3] * SCALE + m1);
                sumr[mt * 2 + 0] += e00 + e01;
                sumr[mt * 2 + 1] += e10 + e11;
                int r0 = wm * 32 + mt * 16 + g;
                *(float2*)(Ab + (size_t)r0 * SS + gc)       = make_float2(e00, e01);
                *(float2*)(Ab + (size_t)(r0 + 8) * SS + gc) = make_float2(e10, e11);
            }
    }
    // reduce over t (quad), then over the 4 n-warps via smem
#pragma unroll
    for (int j = 0; j < 4; j++) {
        sumr[j] += __shfl_xor_sync(0xffffffffu, sumr[j], 1);
        sumr[j] += __shfl_xor_sync(0xffffffffu, sumr[j], 2);
    }
    if (t == 0) {
#pragma unroll
        for (int j = 0; j < 4; j++) {
            int row = wm * 32 + (j >> 1) * 16 + (j & 1) * 8 + g;
            red[wn * 64 + row] = sumr[j];
        }
    }
    __syncthreads();
    if (tid < 64) {
        float s = red[tid] + red[64 + tid] + red[128 + tid] + red[192 + tid];
        invs[tid] = 1.0f / s;
    }
    __syncthreads();

    // --- Pass B: normalize in same sweep (final attn write) + P@V -----------
    float cx[2][3][4];
#pragma unroll
    for (int mt = 0; mt < 2; mt++)
#pragma unroll
        for (int nt = 0; nt < 3; nt++)
#pragma unroll
            for (int i = 0; i < 4; i++) cx[mt][nt][i] = 0.f;

    for (int c = 0; c < NCH; c++) {
        __syncthreads();
        const float* Vc = Vb + (size_t)c * TK * DH;
        for (int i = tid; i < 128 * 24; i += 256) {
            int r = i / 24, c4 = (i % 24) * 4;
            cp16(kvb + (uint32_t)(r * KVB + c4) * 4, Vc + r * DH + c4);
        }
        asm volatile("cp.async.commit_group;" ::: "memory");
        // e tile: read, scale by 1/sum, write FINAL attn, stage tf32 p in smem
        for (int i = tid; i < 64 * 32; i += 256) {
            int r = i >> 5, c4 = (i & 31) * 4;
            float inv = invs[r];
            float* ap = Ab + (size_t)r * SS + c * TK + c4;
            float4 e = *(float4*)ap;
            e.x *= inv; e.y *= inv; e.z *= inv; e.w *= inv;
            *(float4*)ap = e;
            float4 pr = make_float4(tf32r(e.x), tf32r(e.y), tf32r(e.z), tf32r(e.w));
            *(float4*)&pe[r * PED + c4] = pr;
        }
        asm volatile("cp.async.wait_group 0;" ::: "memory");
        __syncthreads();
        // PV: ctx[64,96] += P[64,128] @ V[128,96]
#pragma unroll 4
        for (int kk = 0; kk < TK; kk += 8) {
            uint32_t a[2][4];
#pragma unroll
            for (int mt = 0; mt < 2; mt++) {
                const float* pp = &pe[(wm * 32 + mt * 16 + g) * PED + kk + t];
                a[mt][0] = __float_as_uint(pp[0]);
                a[mt][1] = __float_as_uint(pp[8 * PED]);
                a[mt][2] = __float_as_uint(pp[4]);
                a[mt][3] = __float_as_uint(pp[8 * PED + 4]);
            }
#pragma unroll
            for (int nt = 0; nt < 3; nt++) {
                const float* vp = &KV[(kk + t) * KVB + wn * 24 + nt * 8 + g];
                uint32_t b0 = __float_as_uint(vp[0]);
                uint32_t b1 = __float_as_uint(vp[4 * KVB]);
#pragma unroll
                for (int mt = 0; mt < 2; mt++)
                    MMA4(cx[mt][nt], a[mt], b0, b1);
            }
        }
    }

    // ctx write ([B,S,D] concat-head layout), tf32-rounded for the O-projection
#pragma unroll
    for (int mt = 0; mt < 2; mt++)
#pragma unroll
        for (int nt = 0; nt < 3; nt++) {
            int col = h * DH + wn * 24 + nt * 8 + 2 * t;
#pragma unroll
            for (int hf = 0; hf < 2; hf++) {
                int r = wm * 32 + mt * 16 + hf * 8 + g;
                float2 o = make_float2(tf32r(cx[mt][nt][hf * 2]),
                                       tf32r(cx[mt][nt][hf * 2 + 1]));
                *(float2*)(ctx + ((size_t)b * SS + qt * QT + r) * DM + col) = o;
            }
        }
}

// ---------------- launch ----------------------------------------------------
static float* symaddr(const void* sym) {
    void* p = 0;
    cudaGetSymbolAddress(&p, sym);
    return (float*)p;
}

extern "C" void kernel_launch(void* const* d_in, const int* in_sizes, int n_in,
                              void* d_out, int out_size)
{
    const float* q_in = (const float*)d_in[0];
    const float* k_in = (const float*)d_in[1];
    const float* v_in = (const float*)d_in[2];
    const float* mask = (const float*)d_in[3];
    const float* wq = (const float*)d_in[4];
    const float* bq = (const float*)d_in[5];
    const float* wk = (const float*)d_in[6];
    const float* bk = (const float*)d_in[7];
    const float* wv = (const float*)d_in[8];
    const float* bv = (const float*)d_in[9];
    const float* wo = (const float*)d_in[10];
    const float* bo = (const float*)d_in[11];

    float* pQ   = symaddr(g_Q);
    float* pK   = symaddr(g_K);
    float* pV   = symaddr(g_V);
    float* pctx = symaddr(g_ctx);
    float* pWt  = symaddr(g_Wt);

    const long long OUT_E = (long long)ROWS * DM;
    const long long ATT_E = (long long)BB * HH * SS * (long long)SS;

    float* outp  = (float*)d_out;
    float* attnp;
    if ((long long)out_size >= OUT_E + ATT_E) {
        attnp = (float*)d_out + OUT_E;
    } else if ((long long)out_size == ATT_E) {
        attnp = (float*)d_out;
        outp  = symaddr(g_out_fb);
    } else {
        attnp = symaddr(g_attn_fb);
    }

    static bool attr_done = false;
    if (!attr_done) {
        cudaFuncSetAttribute(attn_kernel, cudaFuncAttributeMaxDynamicSharedMemorySize, ATTN_SMEM);
        cudaFuncSetAttribute(proj_qkv, cudaFuncAttributeMaxDynamicSharedMemorySize, PROJ_SMEM);
        cudaFuncSetAttribute(proj_out, cudaFuncAttributeMaxDynamicSharedMemorySize, PROJ_SMEM);
        attr_done = true;
    }

    // 1) transpose + tf32-round all four weights (one launch)
    wt4_kernel<<<dim3(DM / 32, DM / 32, 4), dim3(32, 8)>>>(wq, wk, wv, wo, pWt);

    // 2) Q/K/V projections fused in one launch (grid.z = 3)
    proj_qkv<<<dim3(DM / PJN, ROWS / PJM, 3), 256, PROJ_SMEM>>>(
        q_in, k_in, v_in, bq, bk, bv, pWt, pQ, pK, pV);

    // 3) attention (QT=64; permuted Q/K frag layouts in pass A)
    attn_kernel<<<dim3(SS / QT, HH, BB), 256, ATTN_SMEM>>>(pQ, pK, pV, mask, attnp, pctx);

    // 4) output projection (ctx already tf32-rounded by attn)
    proj_out<<<dim3(DM / PJN, ROWS / PJM), 256, PROJ_SMEM>>>(
        pctx, pWt + 3 * (size_t)DM * DM, bo, outp);
}

// round 11
// speedup vs baseline: 1.1999x; 1.1999x over previous
#include <cuda_runtime.h>
#include <cstdint>
#include <math.h>

#define BB 4
#define HH 8
#define SS 2048
#define DM 768
#define DH 96
#define ROWS (BB*SS)          // 8192
#define GK DM                 // 768

// ---------------- scratch (device globals; no allocation allowed) ----------
__device__ float g_Q[(size_t)BB*HH*SS*DH];   // fragment-permuted Q
__device__ float g_K[(size_t)BB*HH*SS*DH];   // fragment-permuted K
__device__ float g_V[(size_t)BB*HH*SS*DH];   // head-split V
__device__ float g_ctx[(size_t)ROWS*DM];
__device__ float g_Wt[(size_t)4*DM*DM];
__device__ float g_attn_fb[(size_t)BB*HH*SS*SS];
__device__ float g_out_fb[(size_t)ROWS*DM];

// ---------------- helpers ---------------------------------------------------
__device__ __forceinline__ uint32_t smem_u32(const void* p) {
    uint32_t a;
    asm("{ .reg .u64 t; cvta.to.shared.u64 t, %1; cvt.u32.u64 %0, t; }" : "=r"(a) : "l"(p));
    return a;
}
__device__ __forceinline__ float tf32r(float x) {
    uint32_t u;
    asm("cvt.rna.tf32.f32 %0, %1;" : "=r"(u) : "f"(x));
    return __uint_as_float(u);
}
__device__ __forceinline__ void cp16(uint32_t dst, const void* src) {
    asm volatile("cp.async.cg.shared.global [%0], [%1], 16;" :: "r"(dst), "l"(src));
}

#define MMA4(c, a, b0, b1) \
    asm volatile("mma.sync.aligned.m16n8k8.row.col.f32.tf32.tf32.f32 " \
        "{%0,%1,%2,%3},{%4,%5,%6,%7},{%8,%9},{%0,%1,%2,%3};" \
        : "+f"((c)[0]), "+f"((c)[1]), "+f"((c)[2]), "+f"((c)[3]) \
        : "r"((a)[0]), "r"((a)[1]), "r"((a)[2]), "r"((a)[3]), "r"(b0), "r"(b1))

// FMA-pipe exp. Inputs are O(1) or ~-1e9 (masked).
__device__ __forceinline__ float fexp(float x) {
    float y = x * 1.442695040888963f;
    y = fmaxf(y, -126.0f);
    float t = y + 12582912.0f;
    float n = t - 12582912.0f;
    float f = y - n;
    float p = 1.33335581e-3f;
    p = fmaf(p, f, 9.61812911e-3f);
    p = fmaf(p, f, 5.55041087e-2f);
    p = fmaf(p, f, 2.40226507e-1f);
    p = fmaf(p, f, 6.93147180e-1f);
    p = fmaf(p, f, 1.0f);
    float s = __int_as_float(((int)n + 127) << 23);
    return p * s;
}

// ---------------- weight transpose + tf32 round -----------------------------
__global__ __launch_bounds__(256) void wt4_kernel(
    const float* __restrict__ w0, const float* __restrict__ w1,
    const float* __restrict__ w2, const float* __restrict__ w3,
    float* __restrict__ Wt)
{
    __shared__ float t[32][33];
    int z = blockIdx.z;
    const float* W = (z == 0) ? w0 : (z == 1) ? w1 : (z == 2) ? w2 : w3;
    float* out = Wt + (size_t)z * DM * DM;
    int tx = threadIdx.x, ty = threadIdx.y;
    int bx = blockIdx.x * 32, by = blockIdx.y * 32;
#pragma unroll
    for (int j = 0; j < 32; j += 8)
        t[ty + j][tx] = W[(size_t)(by + ty + j) * DM + bx + tx];
    __syncthreads();
#pragma unroll
    for (int j = 0; j < 32; j += 8)
        out[(size_t)(bx + ty + j) * DM + by + tx] = tf32r(t[tx][ty + j]);
}

// ---------------- projection GEMM via mma.sync tf32 --------------------------
// Tile 128x128, K-chunk 16, 2-stage static-smem cp.async (R9's proven body).
// Epilogue modes: 0 = Q fragment-permuted, 1 = K fragment-permuted,
//                 2 = V head-split, 3 = row-major.
#define PJM 128
#define PJN 128
#define PJK 16
#define ASD 20
#define NCHK (GK / PJK)   // 48

__device__ __forceinline__ void proj_load(
    int tid, int bm, int bn, int c, const float* X, const float* Wt,
    uint32_t abase, uint32_t bbase)
{
    int k0 = c * PJK;
#pragma unroll
    for (int j = 0; j < 2; j++) {
        int i = tid + j * 256;
        int r = i >> 2, c4 = (i & 3) * 4;
        cp16(abase + (uint32_t)(r * ASD + c4) * 4, X + (size_t)(bm + r) * GK + k0 + c4);
    }
#pragma unroll
    for (int j = 0; j < 2; j++) {
        int i = tid + j * 256;
        int r = i >> 2, c4 = (i & 3) * 4;
        cp16(bbase + (uint32_t)(r * ASD + c4) * 4, Wt + (size_t)(bn + r) * GK + k0 + c4);
    }
    asm volatile("cp.async.commit_group;" ::: "memory");
}

__device__ __forceinline__ void proj_body(
    const float* __restrict__ X, const float* __restrict__ Wt,
    const float* __restrict__ bias, float* __restrict__ out, int mode)
{
    __shared__ float As[2][PJM * ASD];
    __shared__ float Bs[2][PJN * ASD];
    const int tid = threadIdx.x, warp = tid >> 5, lane = tid & 31;
    const int g = lane >> 2, t = lane & 3;
    const int bm = blockIdx.y * PJM, bn = blockIdx.x * PJN;
    const int m0 = (warp & 3) * 32, n0 = (warp >> 2) * 64;

    uint32_t ab[2] = { smem_u32(&As[0][0]), smem_u32(&As[1][0]) };
    uint32_t bb[2] = { smem_u32(&Bs[0][0]), smem_u32(&Bs[1][0]) };

    float cf[2][8][4];
#pragma unroll
    for (int mt = 0; mt < 2; mt++)
#pragma unroll
        for (int nt = 0; nt < 8; nt++)
#pragma unroll
            for (int i = 0; i < 4; i++) cf[mt][nt][i] = 0.f;

    proj_load(tid, bm, bn, 0, X, Wt, ab[0], bb[0]);

    for (int c = 0; c < NCHK; c++) {
        int buf = c & 1;
        if (c + 1 < NCHK) {
            proj_load(tid, bm, bn, c + 1, X, Wt, ab[buf ^ 1], bb[buf ^ 1]);
            asm volatile("cp.async.wait_group 1;" ::: "memory");
        } else {
            asm volatile("cp.async.wait_group 0;" ::: "memory");
        }
        __syncthreads();
#pragma unroll
        for (int kk = 0; kk < PJK; kk += 8) {
            uint32_t a[2][4];
#pragma unroll
            for (int mt = 0; mt < 2; mt++) {
                const float* ap = &As[buf][(m0 + mt * 16 + g) * ASD + kk + t];
                a[mt][0] = __float_as_uint(tf32r(ap[0]));
                a[mt][1] = __float_as_uint(tf32r(ap[8 * ASD]));
                a[mt][2] = __float_as_uint(tf32r(ap[4]));
                a[mt][3] = __float_as_uint(tf32r(ap[8 * ASD + 4]));
            }
            uint32_t bf[8][2];
#pragma unroll
            for (int nt = 0; nt < 8; nt++) {
                const float* bp = &Bs[buf][(n0 + nt * 8 + g) * ASD + kk + t];
                bf[nt][0] = __float_as_uint(bp[0]);
                bf[nt][1] = __float_as_uint(bp[4]);
            }
#pragma unroll
            for (int mt = 0; mt < 2; mt++)
#pragma unroll
                for (int nt = 0; nt < 8; nt++)
                    MMA4(cf[mt][nt], a[mt], bf[nt][0], bf[nt][1]);
        }
        __syncthreads();
    }

    // epilogue
#pragma unroll
    for (int mt = 0; mt < 2; mt++) {
        int m_lo = bm + m0 + mt * 16 + g;     // hf=0 row; hf=1 row = m_lo+8
#pragma unroll
        for (int nt = 0; nt < 8; nt++) {
            int col = bn + n0 + nt * 8 + 2 * t;
            float b0v = __ldg(bias + col), b1v = __ldg(bias + col + 1);
            float v0 = cf[mt][nt][0] + b0v;   // (m_lo,   col)
            float v1 = cf[mt][nt][1] + b1v;   // (m_lo,   col+1)
            float v2 = cf[mt][nt][2] + b0v;   // (m_lo+8, col)
            float v3 = cf[mt][nt][3] + b1v;   // (m_lo+8, col+1)
            if (mode == 3) {
                *(float2*)(out + (size_t)m_lo * DM + col)       = make_float2(v0, v1);
                *(float2*)(out + (size_t)(m_lo + 8) * DM + col) = make_float2(v2, v3);
            } else {
                int bdx = m_lo >> 11, s = m_lo & (SS - 1);
                int hh = col / DH, k = col - hh * DH;
                if (mode == 2) {
                    float* vb = out + (((size_t)bdx * HH + hh) * SS + s) * DH + k;
                    *(float2*)(vb)          = make_float2(tf32r(v0), tf32r(v1));
                    *(float2*)(vb + 8 * DH) = make_float2(tf32r(v2), tf32r(v3));
                } else if (mode == 0) {
                    // Q fragment-permuted: [b][h][qt][A=(r>>4)*12+(k>>3)][ln][4]
                    int qt = s >> 6, r = s & 63;
                    int A = (r >> 4) * 12 + (k >> 3);
                    int ln = ((r & 7) << 2) | (k & 3);
                    int e = ((k >> 2) & 1) * 2;
                    size_t base = ((((size_t)bdx * HH + hh) * 32 + qt) * 48 + A) * 128 + ln * 4 + e;
                    *(float2*)(out + base)     = make_float2(tf32r(v0), tf32r(v2));
                    *(float2*)(out + base + 4) = make_float2(tf32r(v1), tf32r(v3));
                } else {
                    // K fragment-permuted: [b][h][c][grp=half*48+wnn*12+kki][ln][4]
                    int c2 = s >> 7, r = s & 127;
                    int grp = ((r >> 4) & 1) * 48 + (r >> 5) * 12 + (k >> 3);
                    int ln = ((r & 7) << 2) | (k & 3);
                    int e1 = (k >> 2) & 1;
                    size_t base = (((size_t)bdx * HH + hh) * 16 + c2) * 12288 + grp * 128 + ln * 4;
                    out[base + e1]     = tf32r(v0);
                    out[base + 2 + e1] = tf32r(v2);
                    out[base + 4 + e1] = tf32r(v1);
                    out[base + 6 + e1] = tf32r(v3);
                }
            }
        }
    }
}

__global__ __launch_bounds__(256) void proj_qkv(
    const float* __restrict__ q_in, const float* __restrict__ k_in,
    const float* __restrict__ v_in,
    const float* __restrict__ bq, const float* __restrict__ bk,
    const float* __restrict__ bv,
    const float* __restrict__ Wt,
    float* __restrict__ outQ, float* __restrict__ outK, float* __restrict__ outV)
{
    int z = blockIdx.z;
    const float* X = (z == 0) ? q_in : (z == 1) ? k_in : v_in;
    const float* bias = (z == 0) ? bq : (z == 1) ? bk : bv;
    float* out = (z == 0) ? outQ : (z == 1) ? outK : outV;
    proj_body(X, Wt + (size_t)z * DM * DM, bias, out, z);
}

__global__ __launch_bounds__(256) void proj_out(
    const float* __restrict__ X, const float* __restrict__ Wt,
    const float* __restrict__ bias, float* __restrict__ out)
{
    proj_body(X, Wt, bias, out, 3);
}

// ---------------- attention (QT=64; gmem-permuted Q/K, linear fills) --------
#define QT 64
#define TK 128
#define NCH (SS / TK)     // 16
#define KVB 104           // V-pass stride
#define PED 132
#define QP_F 6144         // 48 A-groups x 128
#define KV_F 13312        // max(K permuted 12288, V 128x104)
#define PE_F (64*PED)     // 8448
#define ATTN_SMEM ((QP_F + KV_F + PE_F + 128 + 256 + 64) * 4)   // 113408

__global__ __launch_bounds__(256, 2) void attn_kernel(
    const float* __restrict__ gQ, const float* __restrict__ gK,
    const float* __restrict__ gV, const float* __restrict__ mask,
    float* __restrict__ attn, float* __restrict__ ctx)
{
    extern __shared__ float sm[];
    float* QP   = sm;                      // permuted Q (linear copy)
    float* KV   = sm + QP_F;               // permuted K (pass A) / V (pass B)
    float* KP0  = KV;                      // half 0 (6144)
    float* KP1  = KV + 6144;               // half 1 (6144)
    float* pe   = sm + QP_F + KV_F;        // [64][132]
    float* ms   = pe + PE_F;               // [128]
    float* red  = ms + 128;                // [4][64]
    float* invs = red + 256;               // [64]

    const int tid = threadIdx.x;
    const int warp = tid >> 5, lane = tid & 31;
    const int g = lane >> 2, t = lane & 3;
    const int wm = warp & 1, wn = warp >> 1;          // 2(m) x 4(n)
    const int qt = blockIdx.x, h = blockIdx.y, b = blockIdx.z;

    const float* Qp = gQ + (((size_t)b * HH + h) * 32 + qt) * 6144;
    const float* Kb = gK + ((size_t)b * HH + h) * 16 * 12288;
    const float* Vb = gV + ((size_t)b * HH + h) * SS * DH;
    float* Ab = attn + (((size_t)b * HH + h) * SS + (size_t)qt * QT) * (size_t)SS;

    const uint32_t qpb = smem_u32(QP);
    const uint32_t kvb = smem_u32(KV);

    // Q fill: linear coalesced cp.async (24 KB once)
#pragma unroll
    for (int l = 0; l < 6; l++) {
        int i = tid + l * 256;
        cp16(qpb + (uint32_t)i * 16, Qp + i * 4);
    }
    asm volatile("cp.async.commit_group;" ::: "memory");

    const float SCALE = rsqrtf((float)DH);
    float sumr[4] = {0.f, 0.f, 0.f, 0.f};

    // --- Pass A: logits -> exp -> gmem, row sums ---
    for (int c = 0; c < NCH; c++) {
        __syncthreads();
        const float* Kc = Kb + (size_t)c * 12288;
#pragma unroll
        for (int l = 0; l < 12; l++) {
            int i = tid + l * 256;
            cp16(kvb + (uint32_t)i * 16, Kc + i * 4);
        }
        asm volatile("cp.async.commit_group;" ::: "memory");
        if (tid < TK) ms[tid] = mask[(size_t)b * SS + c * TK + tid] * -1e9f;
        asm volatile("cp.async.wait_group 0;" ::: "memory");
        __syncthreads();

        float cf[2][4][4];
#pragma unroll
        for (int mt = 0; mt < 2; mt++)
#pragma unroll
            for (int nt = 0; nt < 4; nt++)
#pragma unroll
                for (int i = 0; i < 4; i++) cf[mt][nt][i] = 0.f;

#pragma unroll
        for (int kki = 0; kki < 12; kki++) {
            float4 q0 = *(float4*)&QP[((wm * 2 + 0) * 12 + kki) * 128 + lane * 4];
            float4 q1 = *(float4*)&QP[((wm * 2 + 1) * 12 + kki) * 128 + lane * 4];
            float4 k0 = *(float4*)&KP0[(wn * 12 + kki) * 128 + lane * 4];
            float4 k1 = *(float4*)&KP1[(wn * 12 + kki) * 128 + lane * 4];
            uint32_t a0[4] = {__float_as_uint(q0.x), __float_as_uint(q0.y),
                              __float_as_uint(q0.z), __float_as_uint(q0.w)};
            uint32_t a1[4] = {__float_as_uint(q1.x), __float_as_uint(q1.y),
                              __float_as_uint(q1.z), __float_as_uint(q1.w)};
            MMA4(cf[0][0], a0, __float_as_uint(k0.x), __float_as_uint(k0.y));
            MMA4(cf[0][1], a0, __float_as_uint(k0.z), __float_as_uint(k0.w));
            MMA4(cf[0][2], a0, __float_as_uint(k1.x), __float_as_uint(k1.y));
            MMA4(cf[0][3], a0, __float_as_uint(k1.z), __float_as_uint(k1.w));
            MMA4(cf[1][0], a1, __float_as_uint(k0.x), __float_as_uint(k0.y));
            MMA4(cf[1][1], a1, __float_as_uint(k0.z), __float_as_uint(k0.w));
            MMA4(cf[1][2], a1, __float_as_uint(k1.x), __float_as_uint(k1.y));
            MMA4(cf[1][3], a1, __float_as_uint(k1.z), __float_as_uint(k1.w));
        }

#pragma unroll
        for (int mt = 0; mt < 2; mt++)
#pragma unroll
            for (int nt = 0; nt < 4; nt++) {
                int lc = wn * 32 + nt * 8 + 2 * t;
                float m0 = ms[lc], m1 = ms[lc + 1];
                int gc = c * TK + lc;
                float e00 = fexp(cf[mt][nt][0] * SCALE + m0);
                float e01 = fexp(cf[mt][nt][1] * SCALE + m1);
                float e10 = fexp(cf[mt][nt][2] * SCALE + m0);
                float e11 = fexp(cf[mt][nt][3] * SCALE + m1);
                sumr[mt * 2 + 0] += e00 + e01;
                sumr[mt * 2 + 1] += e10 + e11;
                int r0 = wm * 32 + mt * 16 + g;
                *(float2*)(Ab + (size_t)r0 * SS + gc)       = make_float2(e00, e01);
                *(float2*)(Ab + (size_t)(r0 + 8) * SS + gc) = make_float2(e10, e11);
            }
    }
    // reduce over t (quad), then over the 4 n-warps via smem
#pragma unroll
    for (int j = 0; j < 4; j++) {
        sumr[j] += __shfl_xor_sync(0xffffffffu, sumr[j], 1);
        sumr[j] += __shfl_xor_sync(0xffffffffu, sumr[j], 2);
    }
    if (t == 0) {
#pragma unroll
        for (int j = 0; j < 4; j++) {
            int row = wm * 32 + (j >> 1) * 16 + (j & 1) * 8 + g;
            red[wn * 64 + row] = sumr[j];
        }
    }
    __syncthreads();
    if (tid < 64) {
        float s = red[tid] + red[64 + tid] + red[128 + tid] + red[192 + tid];
        invs[tid] = 1.0f / s;
    }
    __syncthreads();

    // --- Pass B: normalize in same sweep (final attn write) + P@V -----------
    float cx[2][3][4];
#pragma unroll
    for (int mt = 0; mt < 2; mt++)
#pragma unroll
        for (int nt = 0; nt < 3; nt++)
#pragma unroll
            for (int i = 0; i < 4; i++) cx[mt][nt][i] = 0.f;

    for (int c = 0; c < NCH; c++) {
        __syncthreads();
        const float* Vc = Vb + (size_t)c * TK * DH;
        for (int i = tid; i < 128 * 24; i += 256) {
            int r = i / 24, c4 = (i % 24) * 4;
            cp16(kvb + (uint32_t)(r * KVB + c4) * 4, Vc + r * DH + c4);
        }
        asm volatile("cp.async.commit_group;" ::: "memory");
        // e tile: read, scale by 1/sum, write FINAL attn, stage tf32 p in smem
        for (int i = tid; i < 64 * 32; i += 256) {
            int r = i >> 5, c4 = (i & 31) * 4;
            float inv = invs[r];
            float* ap = Ab + (size_t)r * SS + c * TK + c4;
            float4 e = *(float4*)ap;
            e.x *= inv; e.y *= inv; e.z *= inv; e.w *= inv;
            *(float4*)ap = e;
            float4 pr = make_float4(tf32r(e.x), tf32r(e.y), tf32r(e.z), tf32r(e.w));
            *(float4*)&pe[r * PED + c4] = pr;
        }
        asm volatile("cp.async.wait_group 0;" ::: "memory");
        __syncthreads();
        // PV: ctx[64,96] += P[64,128] @ V[128,96]
#pragma unroll 4
        for (int kk = 0; kk < TK; kk += 8) {
            uint32_t a[2][4];
#pragma unroll
            for (int mt = 0; mt < 2; mt++) {
                const float* pp = &pe[(wm * 32 + mt * 16 + g) * PED + kk + t];
                a[mt][0] = __float_as_uint(pp[0]);
                a[mt][1] = __float_as_uint(pp[8 * PED]);
                a[mt][2] = __float_as_uint(pp[4]);
                a[mt][3] = __float_as_uint(pp[8 * PED + 4]);
            }
#pragma unroll
            for (int nt = 0; nt < 3; nt++) {
                const float* vp = &KV[(kk + t) * KVB + wn * 24 + nt * 8 + g];
                uint32_t b0 = __float_as_uint(vp[0]);
                uint32_t b1 = __float_as_uint(vp[4 * KVB]);
#pragma unroll
                for (int mt = 0; mt < 2; mt++)
                    MMA4(cx[mt][nt], a[mt], b0, b1);
            }
        }
    }

    // ctx write ([B,S,D] concat-head layout), tf32-rounded for the O-projection
#pragma unroll
    for (int mt = 0; mt < 2; mt++)
#pragma unroll
        for (int nt = 0; nt < 3; nt++) {
            int col = h * DH + wn * 24 + nt * 8 + 2 * t;
#pragma unroll
            for (int hf = 0; hf < 2; hf++) {
                int r = wm * 32 + mt * 16 + hf * 8 + g;
                float2 o = make_float2(tf32r(cx[mt][nt][hf * 2]),
                                       tf32r(cx[mt][nt][hf * 2 + 1]));
                *(float2*)(ctx + ((size_t)b * SS + qt * QT + r) * DM + col) = o;
            }
        }
}

// ---------------- launch ----------------------------------------------------
static float* symaddr(const void* sym) {
    void* p = 0;
    cudaGetSymbolAddress(&p, sym);
    return (float*)p;
}

extern "C" void kernel_launch(void* const* d_in, const int* in_sizes, int n_in,
                              void* d_out, int out_size)
{
    const float* q_in = (const float*)d_in[0];
    const float* k_in = (const float*)d_in[1];
    const float* v_in = (const float*)d_in[2];
    const float* mask = (const float*)d_in[3];
    const float* wq = (const float*)d_in[4];
    const float* bq = (const float*)d_in[5];
    const float* wk = (const float*)d_in[6];
    const float* bk = (const float*)d_in[7];
    const float* wv = (const float*)d_in[8];
    const float* bv = (const float*)d_in[9];
    const float* wo = (const float*)d_in[10];
    const float* bo = (const float*)d_in[11];

    float* pQ   = symaddr(g_Q);
    float* pK   = symaddr(g_K);
    float* pV   = symaddr(g_V);
    float* pctx = symaddr(g_ctx);
    float* pWt  = symaddr(g_Wt);

    const long long OUT_E = (long long)ROWS * DM;
    const long long ATT_E = (long long)BB * HH * SS * (long long)SS;

    float* outp  = (float*)d_out;
    float* attnp;
    if ((long long)out_size >= OUT_E + ATT_E) {
        attnp = (float*)d_out + OUT_E;
    } else if ((long long)out_size == ATT_E) {
        attnp = (float*)d_out;
        outp  = symaddr(g_out_fb);
    } else {
        attnp = symaddr(g_attn_fb);
    }

    static bool attr_done = false;
    if (!attr_done) {
        cudaFuncSetAttribute(attn_kernel, cudaFuncAttributeMaxDynamicSharedMemorySize, ATTN_SMEM);
        attr_done = true;
    }

    // 1) transpose + tf32-round all four weights (one launch)
    wt4_kernel<<<dim3(DM / 32, DM / 32, 4), dim3(32, 8)>>>(wq, wk, wv, wo, pWt);

    // 2) fused Q/K/V projections; epilogue writes Q/K fragment-permuted, V head-split
    proj_qkv<<<dim3(DM / PJN, ROWS / PJM, 3), 256>>>(
        q_in, k_in, v_in, bq, bk, bv, pWt, pQ, pK, pV);

    // 3) attention (linear cp.async fills of permuted Q/K; LDS.128 mainloop)
    attn_kernel<<<dim3(SS / QT, HH, BB), 256, ATTN_SMEM>>>(pQ, pK, pV, mask, attnp, pctx);

    // 4) output projection
    proj_out<<<dim3(DM / PJN, ROWS / PJM), 256>>>(pctx, pWt + 3 * (size_t)DM * DM, bo, outp);
}

// round 13
// speedup vs baseline: 1.2780x; 1.0651x over previous
#include <cuda_runtime.h>
#include <cstdint>
#include <math.h>

#define BB 4
#define HH 8
#define SS 2048
#define DM 768
#define DH 96
#define ROWS (BB*SS)          // 8192
#define GK DM                 // 768

// ---------------- scratch (device globals; no allocation allowed) ----------
__device__ float g_Q[(size_t)BB*HH*SS*DH];   // fragment-permuted Q
__device__ float g_K[(size_t)BB*HH*SS*DH];   // fragment-permuted K
__device__ float g_V[(size_t)BB*HH*SS*DH];   // fragment-permuted V
__device__ float g_ctx[(size_t)ROWS*DM];
__device__ float g_Wt[(size_t)4*DM*DM];      // fragment-permuted weights
__device__ float g_attn_fb[(size_t)BB*HH*SS*SS];
__device__ float g_out_fb[(size_t)ROWS*DM];

// ---------------- helpers ---------------------------------------------------
__device__ __forceinline__ uint32_t smem_u32(const void* p) {
    uint32_t a;
    asm("{ .reg .u64 t; cvta.to.shared.u64 t, %1; cvt.u32.u64 %0, t; }" : "=r"(a) : "l"(p));
    return a;
}
__device__ __forceinline__ float tf32r(float x) {
    uint32_t u;
    asm("cvt.rna.tf32.f32 %0, %1;" : "=r"(u) : "f"(x));
    return __uint_as_float(u);
}
__device__ __forceinline__ void cp16(uint32_t dst, const void* src) {
    asm volatile("cp.async.cg.shared.global [%0], [%1], 16;" :: "r"(dst), "l"(src));
}

#define MMA4(c, a, b0, b1) \
    asm volatile("mma.sync.aligned.m16n8k8.row.col.f32.tf32.tf32.f32 " \
        "{%0,%1,%2,%3},{%4,%5,%6,%7},{%8,%9},{%0,%1,%2,%3};" \
        : "+f"((c)[0]), "+f"((c)[1]), "+f"((c)[2]), "+f"((c)[3]) \
        : "r"((a)[0]), "r"((a)[1]), "r"((a)[2]), "r"((a)[3]), "r"(b0), "r"(b1))

// FMA-pipe exp. Inputs are O(1) or ~-1e9 (masked).
__device__ __forceinline__ float fexp(float x) {
    float y = x * 1.442695040888963f;
    y = fmaxf(y, -126.0f);
    float t = y + 12582912.0f;
    float n = t - 12582912.0f;
    float f = y - n;
    float p = 1.33335581e-3f;
    p = fmaf(p, f, 9.61812911e-3f);
    p = fmaf(p, f, 5.55041087e-2f);
    p = fmaf(p, f, 2.40226507e-1f);
    p = fmaf(p, f, 6.93147180e-1f);
    p = fmaf(p, f, 1.0f);
    float s = __int_as_float(((int)n + 127) << 23);
    return p * s;
}

// ---------------- weight transpose -> fragment-permuted + tf32 round --------
// WP[(kki*96 + n8)*64 + (g*4+t)*2 + e] = tf32(W[k][n]),
//   kki=k>>3, t=k&3, e=(k>>2)&1, n8=n>>3, g=n&7
__global__ __launch_bounds__(256) void wt4_kernel(
    const float* __restrict__ w0, const float* __restrict__ w1,
    const float* __restrict__ w2, const float* __restrict__ w3,
    float* __restrict__ Wt)
{
    __shared__ float t[32][33];
    int z = blockIdx.z;
    const float* W = (z == 0) ? w0 : (z == 1) ? w1 : (z == 2) ? w2 : w3;
    float* out = Wt + (size_t)z * DM * DM;
    int tx = threadIdx.x, ty = threadIdx.y;
    int bx = blockIdx.x * 32, by = blockIdx.y * 32;
#pragma unroll
    for (int j = 0; j < 32; j += 8)
        t[ty + j][tx] = W[(size_t)(by + ty + j) * DM + bx + tx];
    __syncthreads();
#pragma unroll
    for (int j = 0; j < 32; j += 8) {
        int n = bx + ty + j, k = by + tx;
        int kki = k >> 3, tt = k & 3, e = (k >> 2) & 1;
        int n8 = n >> 3, g = n & 7;
        out[(size_t)(kki * 96 + n8) * 64 + (g * 4 + tt) * 2 + e] = tf32r(t[tx][ty + j]);
    }
}

// ---------------- projection GEMM via mma.sync tf32 --------------------------
// Tile 128x128, K-chunk 16, 2-stage cp.async. B (weights) fragment-permuted.
// Epilogue modes: 0=Q frag-perm, 1=K frag-perm, 2=V frag-perm, 3=row-major.
#define PJM 128
#define PJN 128
#define PJK 16
#define ASD 20
#define BSTG 2048              // B stage floats: 2 kki x 16 n8 x 64
#define NCHK (GK / PJK)        // 48

__device__ __forceinline__ void proj_load(
    int tid, int bm, int bn, int c, const float* X, const float* WP,
    uint32_t abase, uint32_t bbase)
{
    int k0 = c * PJK;
#pragma unroll
    for (int j = 0; j < 2; j++) {
        int i = tid + j * 256;
        int r = i >> 2, c4 = (i & 3) * 4;
        cp16(abase + (uint32_t)(r * ASD + c4) * 4, X + (size_t)(bm + r) * GK + k0 + c4);
    }
    // B: two linear 1024-float blocks (kki = 2c, 2c+1; n8 = bn/8 .. +15)
    const float* Wc = WP + (size_t)(2 * c * 96 + (bn >> 3)) * 64;
#pragma unroll
    for (int j = 0; j < 2; j++) {
        int i = tid + j * 256;           // 0..511
        int jj = i >> 8;                 // kki block
        int off = (i & 255) * 4;
        cp16(bbase + (uint32_t)(jj * 1024 + off) * 4, Wc + (size_t)jj * 96 * 64 + off);
    }
    asm volatile("cp.async.commit_group;" ::: "memory");
}

__device__ __forceinline__ void proj_body(
    const float* __restrict__ X, const float* __restrict__ WP,
    const float* __restrict__ bias, float* __restrict__ out, int mode)
{
    __shared__ float As[2][PJM * ASD];
    __shared__ float Bs[2][BSTG];
    const int tid = threadIdx.x, warp = tid >> 5, lane = tid & 31;
    const int g = lane >> 2, t = lane & 3;
    const int bm = blockIdx.y * PJM, bn = blockIdx.x * PJN;
    const int m0 = (warp & 3) * 32, n0 = (warp >> 2) * 64;
    const int n8b = (warp >> 2) * 8;     // n8 local base

    uint32_t ab[2] = { smem_u32(&As[0][0]), smem_u32(&As[1][0]) };
    uint32_t bb[2] = { smem_u32(&Bs[0][0]), smem_u32(&Bs[1][0]) };

    float cf[2][8][4];
#pragma unroll
    for (int mt = 0; mt < 2; mt++)
#pragma unroll
        for (int nt = 0; nt < 8; nt++)
#pragma unroll
            for (int i = 0; i < 4; i++) cf[mt][nt][i] = 0.f;

    proj_load(tid, bm, bn, 0, X, WP, ab[0], bb[0]);

    for (int c = 0; c < NCHK; c++) {
        int buf = c & 1;
        if (c + 1 < NCHK) {
            proj_load(tid, bm, bn, c + 1, X, WP, ab[buf ^ 1], bb[buf ^ 1]);
            asm volatile("cp.async.wait_group 1;" ::: "memory");
        } else {
            asm volatile("cp.async.wait_group 0;" ::: "memory");
        }
        __syncthreads();
#pragma unroll
        for (int kk = 0; kk < PJK; kk += 8) {
            uint32_t a[2][4];
#pragma unroll
            for (int mt = 0; mt < 2; mt++) {
                const float* ap = &As[buf][(m0 + mt * 16 + g) * ASD + kk + t];
                a[mt][0] = __float_as_uint(tf32r(ap[0]));
                a[mt][1] = __float_as_uint(tf32r(ap[8 * ASD]));
                a[mt][2] = __float_as_uint(tf32r(ap[4]));
                a[mt][3] = __float_as_uint(tf32r(ap[8 * ASD + 4]));
            }
            uint32_t bf[8][2];
#pragma unroll
            for (int nt = 0; nt < 8; nt++) {
                float2 bv = *(float2*)&Bs[buf][((kk >> 3) * 16 + n8b + nt) * 64 + lane * 2];
                bf[nt][0] = __float_as_uint(bv.x);
                bf[nt][1] = __float_as_uint(bv.y);
            }
#pragma unroll
            for (int mt = 0; mt < 2; mt++)
#pragma unroll
                for (int nt = 0; nt < 8; nt++)
                    MMA4(cf[mt][nt], a[mt], bf[nt][0], bf[nt][1]);
        }
        __syncthreads();
    }

    // epilogue
#pragma unroll
    for (int mt = 0; mt < 2; mt++) {
        int m_lo = bm + m0 + mt * 16 + g;
#pragma unroll
        for (int nt = 0; nt < 8; nt++) {
            int col = bn + n0 + nt * 8 + 2 * t;
            float b0v = __ldg(bias + col), b1v = __ldg(bias + col + 1);
            float v0 = cf[mt][nt][0] + b0v;   // (m_lo,   col)
            float v1 = cf[mt][nt][1] + b1v;   // (m_lo,   col+1)
            float v2 = cf[mt][nt][2] + b0v;   // (m_lo+8, col)
            float v3 = cf[mt][nt][3] + b1v;   // (m_lo+8, col+1)
            if (mode == 3) {
                *(float2*)(out + (size_t)m_lo * DM + col)       = make_float2(v0, v1);
                *(float2*)(out + (size_t)(m_lo + 8) * DM + col) = make_float2(v2, v3);
            } else {
                int bdx = m_lo >> 11, s = m_lo & (SS - 1);
                int hh = col / DH, k = col - hh * DH;
                if (mode == 2) {
                    // V fragment-permuted: [b][h][c][(kki*12+n8)*64 + (g*4+t)*2 + e]
                    int c2 = s >> 7, tl = s & 127;
                    int kki = tl >> 3, tt = tl & 3, e = (tl >> 2) & 1;
                    int n8 = k >> 3, gg = k & 7;
                    size_t base = (((size_t)bdx * HH + hh) * 16 + c2) * 12288;
                    out[base + (size_t)(kki * 12 + n8) * 64 + (gg * 4 + tt) * 2 + e]             = tf32r(v0);
                    out[base + (size_t)(kki * 12 + n8) * 64 + ((gg + 1) * 4 + tt) * 2 + e]       = tf32r(v1);
                    out[base + (size_t)((kki + 1) * 12 + n8) * 64 + (gg * 4 + tt) * 2 + e]       = tf32r(v2);
                    out[base + (size_t)((kki + 1) * 12 + n8) * 64 + ((gg + 1) * 4 + tt) * 2 + e] = tf32r(v3);
                } else if (mode == 0) {
                    // Q fragment-permuted: [b][h][qt][A=(r>>4)*12+(k>>3)][ln][4]
                    int qt = s >> 6, r = s & 63;
                    int A = (r >> 4) * 12 + (k >> 3);
                    int ln = ((r & 7) << 2) | (k & 3);
                    int e = ((k >> 2) & 1) * 2;
                    size_t base = ((((size_t)bdx * HH + hh) * 32 + qt) * 48 + A) * 128 + ln * 4 + e;
                    *(float2*)(out + base)     = make_float2(tf32r(v0), tf32r(v2));
                    *(float2*)(out + base + 4) = make_float2(tf32r(v1), tf32r(v3));
                } else {
                    // K fragment-permuted: [b][h][c][grp=half*48+wnn*12+kki][ln][4]
                    int c2 = s >> 7, r = s & 127;
                    int grp = ((r >> 4) & 1) * 48 + (r >> 5) * 12 + (k >> 3);
                    int ln = ((r & 7) << 2) | (k & 3);
                    int e1 = (k >> 2) & 1;
                    size_t base = (((size_t)bdx * HH + hh) * 16 + c2) * 12288 + grp * 128 + ln * 4;
                    out[base + e1]     = tf32r(v0);
                    out[base + 2 + e1] = tf32r(v2);
                    out[base + 4 + e1] = tf32r(v1);
                    out[base + 6 + e1] = tf32r(v3);
                }
            }
        }
    }
}

__global__ __launch_bounds__(256) void proj_qkv(
    const float* __restrict__ q_in, const float* __restrict__ k_in,
    const float* __restrict__ v_in,
    const float* __restrict__ bq, const float* __restrict__ bk,
    const float* __restrict__ bv,
    const float* __restrict__ Wt,
    float* __restrict__ outQ, float* __restrict__ outK, float* __restrict__ outV)
{
    int z = blockIdx.z;
    const float* X = (z == 0) ? q_in : (z == 1) ? k_in : v_in;
    const float* bias = (z == 0) ? bq : (z == 1) ? bk : bv;
    float* out = (z == 0) ? outQ : (z == 1) ? outK : outV;
    proj_body(X, Wt + (size_t)z * DM * DM, bias, out, z);
}

__global__ __launch_bounds__(256) void proj_out(
    const float* __restrict__ X, const float* __restrict__ Wt,
    const float* __restrict__ bias, float* __restrict__ out)
{
    proj_body(X, Wt, bias, out, 3);
}

// ---------------- attention (all operands fragment-permuted) ----------------
#define QT 64
#define TK 128
#define NCH (SS / TK)     // 16
#define PEA 132           // pe A-group stride (pad kills broadcast conflicts)
#define QP_F 6144
#define KV_F 12288        // K permuted / V permuted (both 12288)
#define PE_F (64*PEA)     // 8448
#define ATTN_SMEM ((QP_F + KV_F + PE_F + 128 + 256 + 64) * 4)   // 109312

__global__ __launch_bounds__(256, 2) void attn_kernel(
    const float* __restrict__ gQ, const float* __restrict__ gK,
    const float* __restrict__ gV, const float* __restrict__ mask,
    float* __restrict__ attn, float* __restrict__ ctx)
{
    extern __shared__ float sm[];
    float* QP   = sm;
    float* KV   = sm + QP_F;               // K perm (pass A) / V perm (pass B)
    float* KP0  = KV;
    float* KP1  = KV + 6144;
    float* pe   = sm + QP_F + KV_F;        // fragment-permuted P
    float* ms   = pe + PE_F;               // [128]
    float* red  = ms + 128;                // [4][64]
    float* invs = red + 256;               // [64]

    const int tid = threadIdx.x;
    const int warp = tid >> 5, lane = tid & 31;
    const int g = lane >> 2, t = lane & 3;
    const int wm = warp & 1, wn = warp >> 1;          // 2(m) x 4(n)
    const int qt = blockIdx.x, h = blockIdx.y, b = blockIdx.z;

    const float* Qp = gQ + (((size_t)b * HH + h) * 32 + qt) * 6144;
    const float* Kb = gK + ((size_t)b * HH + h) * 16 * 12288;
    const float* Vb = gV + ((size_t)b * HH + h) * 16 * 12288;
    float* Ab = attn + (((size_t)b * HH + h) * SS + (size_t)qt * QT) * (size_t)SS;

    const uint32_t qpb = smem_u32(QP);
    const uint32_t kvb = smem_u32(KV);

    // Q fill: linear coalesced cp.async (24 KB once)
#pragma unroll
    for (int l = 0; l < 6; l++) {
        int i = tid + l * 256;
        cp16(qpb + (uint32_t)i * 16, Qp + i * 4);
    }
    asm volatile("cp.async.commit_group;" ::: "memory");

    const float SCALE = rsqrtf((float)DH);
    float sumr[4] = {0.f, 0.f, 0.f, 0.f};

    // --- Pass A: logits -> exp -> gmem, row sums ---
    for (int c = 0; c < NCH; c++) {
        __syncthreads();
        const float* Kc = Kb + (size_t)c * 12288;
#pragma unroll
        for (int l = 0; l < 12; l++) {
            int i = tid + l * 256;
            cp16(kvb + (uint32_t)i * 16, Kc + i * 4);
        }
        asm volatile("cp.async.commit_group;" ::: "memory");
        if (tid < TK) ms[tid] = mask[(size_t)b * SS + c * TK + tid] * -1e9f;
        asm volatile("cp.async.wait_group 0;" ::: "memory");
        __syncthreads();

        float cf[2][4][4];
#pragma unroll
        for (int mt = 0; mt < 2; mt++)
#pragma unroll
            for (int nt = 0; nt < 4; nt++)
#pragma unroll
                for (int i = 0; i < 4; i++) cf[mt][nt][i] = 0.f;

#pragma unroll
        for (int kki = 0; kki < 12; kki++) {
            float4 q0 = *(float4*)&QP[((wm * 2 + 0) * 12 + kki) * 128 + lane * 4];
            float4 q1 = *(float4*)&QP[((wm * 2 + 1) * 12 + kki) * 128 + lane * 4];
            float4 k0 = *(float4*)&KP0[(wn * 12 + kki) * 128 + lane * 4];
            float4 k1 = *(float4*)&KP1[(wn * 12 + kki) * 128 + lane * 4];
            uint32_t a0[4] = {__float_as_uint(q0.x), __float_as_uint(q0.y),
                              __float_as_uint(q0.z), __float_as_uint(q0.w)};
            uint32_t a1[4] = {__float_as_uint(q1.x), __float_as_uint(q1.y),
                              __float_as_uint(q1.z), __float_as_uint(q1.w)};
            MMA4(cf[0][0], a0, __float_as_uint(k0.x), __float_as_uint(k0.y));
            MMA4(cf[0][1], a0, __float_as_uint(k0.z), __float_as_uint(k0.w));
            MMA4(cf[0][2], a0, __float_as_uint(k1.x), __float_as_uint(k1.y));
            MMA4(cf[0][3], a0, __float_as_uint(k1.z), __float_as_uint(k1.w));
            MMA4(cf[1][0], a1, __float_as_uint(k0.x), __float_as_uint(k0.y));
            MMA4(cf[1][1], a1, __float_as_uint(k0.z), __float_as_uint(k0.w));
            MMA4(cf[1][2], a1, __float_as_uint(k1.x), __float_as_uint(k1.y));
            MMA4(cf[1][3], a1, __float_as_uint(k1.z), __float_as_uint(k1.w));
        }

#pragma unroll
        for (int mt = 0; mt < 2; mt++)
#pragma unroll
            for (int nt = 0; nt < 4; nt++) {
                int lc = wn * 32 + nt * 8 + 2 * t;
                float m0 = ms[lc], m1 = ms[lc + 1];
                int gc = c * TK + lc;
                float e00 = fexp(cf[mt][nt][0] * SCALE + m0);
                float e01 = fexp(cf[mt][nt][1] * SCALE + m1);
                float e10 = fexp(cf[mt][nt][2] * SCALE + m0);
                float e11 = fexp(cf[mt][nt][3] * SCALE + m1);
                sumr[mt * 2 + 0] += e00 + e01;
                sumr[mt * 2 + 1] += e10 + e11;
                int r0 = wm * 32 + mt * 16 + g;
                *(float2*)(Ab + (size_t)r0 * SS + gc)       = make_float2(e00, e01);
                *(float2*)(Ab + (size_t)(r0 + 8) * SS + gc) = make_float2(e10, e11);
            }
    }
    // reduce over t (quad), then over the 4 n-warps via smem
#pragma unroll
    for (int j = 0; j < 4; j++) {
        sumr[j] += __shfl_xor_sync(0xffffffffu, sumr[j], 1);
        sumr[j] += __shfl_xor_sync(0xffffffffu, sumr[j], 2);
    }
    if (t == 0) {
#pragma unroll
        for (int j = 0; j < 4; j++) {
            int row = wm * 32 + (j >> 1) * 16 + (j & 1) * 8 + g;
            red[wn * 64 + row] = sumr[j];
        }
    }
    __syncthreads();
    if (tid < 64) {
        float s = red[tid] + red[64 + tid] + red[128 + tid] + red[192 + tid];
        invs[tid] = 1.0f / s;
    }
    __syncthreads();

    // --- Pass B: normalize (final attn write) + P@V, pe fragment-permuted ---
    float cx[2][3][4];
#pragma unroll
    for (int mt = 0; mt < 2; mt++)
#pragma unroll
        for (int nt = 0; nt < 3; nt++)
#pragma unroll
            for (int i = 0; i < 4; i++) cx[mt][nt][i] = 0.f;

    for (int c = 0; c < NCH; c++) {
        __syncthreads();
        const float* Vc = Vb + (size_t)c * 12288;
#pragma unroll
        for (int l = 0; l < 12; l++) {
            int i = tid + l * 256;
            cp16(kvb + (uint32_t)i * 16, Vc + i * 4);
        }
        asm volatile("cp.async.commit_group;" ::: "memory");
        // e tile: read, scale, write FINAL attn; stage tf32 p fragment-permuted
#pragma unroll
        for (int it = 0; it < 8; it++) {
            int i = tid + it * 256;
            int r = i >> 5, l = i & 31;
            float inv = invs[r];
            float* ap = Ab + (size_t)r * SS + c * TK + l * 4;
            float4 e = *(float4*)ap;
            e.x *= inv; e.y *= inv; e.z *= inv; e.w *= inv;
            *(float4*)ap = e;
            int wmmt = r >> 4, hf = (r >> 3) & 1, gq = r & 7;
            int kki = l >> 1, ee = l & 1;
            float* pb = &pe[(wmmt * 16 + kki) * PEA + gq * 16 + hf + 2 * ee];
            pb[0]  = tf32r(e.x);
            pb[4]  = tf32r(e.y);
            pb[8]  = tf32r(e.z);
            pb[12] = tf32r(e.w);
        }
        asm volatile("cp.async.wait_group 0;" ::: "memory");
        __syncthreads();
        // PV: ctx[64,96] += P[64,128] @ V[128,96]; a = LDS.128, b = LDS.64
#pragma unroll 4
        for (int kki = 0; kki < 16; kki++) {
            uint32_t a[2][4];
#pragma unroll
            for (int mt = 0; mt < 2; mt++) {
                float4 av = *(float4*)&pe[((wm * 2 + mt) * 16 + kki) * PEA + lane * 4];
                a[mt][0] = __float_as_uint(av.x);
                a[mt][1] = __float_as_uint(av.y);
                a[mt][2] = __float_as_uint(av.z);
                a[mt][3] = __float_as_uint(av.w);
            }
#pragma unroll
            for (int nt = 0; nt < 3; nt++) {
                float2 bv = *(float2*)&KV[(kki * 12 + wn * 3 + nt) * 64 + lane * 2];
                uint32_t b0 = __float_as_uint(bv.x);
                uint32_t b1 = __float_as_uint(bv.y);
#pragma unroll
                for (int mt = 0; mt < 2; mt++)
                    MMA4(cx[mt][nt], a[mt], b0, b1);
            }
        }
    }

    // ctx write ([B,S,D] concat-head layout), tf32-rounded for the O-projection
#pragma unroll
    for (int mt = 0; mt < 2; mt++)
#pragma unroll
        for (int nt = 0; nt < 3; nt++) {
            int col = h * DH + wn * 24 + nt * 8 + 2 * t;
#pragma unroll
            for (int hf = 0; hf < 2; hf++) {
                int r = wm * 32 + mt * 16 + hf * 8 + g;
                float2 o = make_float2(tf32r(cx[mt][nt][hf * 2]),
                                       tf32r(cx[mt][nt][hf * 2 + 1]));
                *(float2*)(ctx + ((size_t)b * SS + qt * QT + r) * DM + col) = o;
            }
        }
}

// ---------------- launch ----------------------------------------------------
static float* symaddr(const void* sym) {
    void* p = 0;
    cudaGetSymbolAddress(&p, sym);
    return (float*)p;
}

extern "C" void kernel_launch(void* const* d_in, const int* in_sizes, int n_in,
                              void* d_out, int out_size)
{
    const float* q_in = (const float*)d_in[0];
    const float* k_in = (const float*)d_in[1];
    const float* v_in = (const float*)d_in[2];
    const float* mask = (const float*)d_in[3];
    const float* wq = (const float*)d_in[4];
    const float* bq = (const float*)d_in[5];
    const float* wk = (const float*)d_in[6];
    const float* bk = (const float*)d_in[7];
    const float* wv = (const float*)d_in[8];
    const float* bv = (const float*)d_in[9];
    const float* wo = (const float*)d_in[10];
    const float* bo = (const float*)d_in[11];

    float* pQ   = symaddr(g_Q);
    float* pK   = symaddr(g_K);
    float* pV   = symaddr(g_V);
    float* pctx = symaddr(g_ctx);
    float* pWt  = symaddr(g_Wt);

    const long long OUT_E = (long long)ROWS * DM;
    const long long ATT_E = (long long)BB * HH * SS * (long long)SS;

    float* outp  = (float*)d_out;
    float* attnp;
    if ((long long)out_size >= OUT_E + ATT_E) {
        attnp = (float*)d_out + OUT_E;
    } else if ((long long)out_size == ATT_E) {
        attnp = (float*)d_out;
        outp  = symaddr(g_out_fb);
    } else {
        attnp = symaddr(g_attn_fb);
    }

    static bool attr_done = false;
    if (!attr_done) {
        cudaFuncSetAttribute(attn_kernel, cudaFuncAttributeMaxDynamicSharedMemorySize, ATTN_SMEM);
        attr_done = true;
    }

    // 1) weights -> fragment-permuted + tf32 (one launch)
    wt4_kernel<<<dim3(DM / 32, DM / 32, 4), dim3(32, 8)>>>(wq, wk, wv, wo, pWt);

    // 2) fused Q/K/V projections; epilogues write Q/K/V fragment-permuted
    proj_qkv<<<dim3(DM / PJN, ROWS / PJM, 3), 256>>>(
        q_in, k_in, v_in, bq, bk, bv, pWt, pQ, pK, pV);

    // 3) attention (linear fills; LDS.128/LDS.64 mainloops)
    attn_kernel<<<dim3(SS / QT, HH, BB), 256, ATTN_SMEM>>>(pQ, pK, pV, mask, attnp, pctx);

    // 4) output projection
    proj_out<<<dim3(DM / PJN, ROWS / PJM), 256>>>(pctx, pWt + 3 * (size_t)DM * DM, bo, outp);
}

// round 14
// speedup vs baseline: 1.2929x; 1.0117x over previous
#include <cuda_runtime.h>
#include <cstdint>
#include <math.h>

#define BB 4
#define HH 8
#define SS 2048
#define DM 768
#define DH 96
#define ROWS (BB*SS)          // 8192
#define GK DM                 // 768

// ---------------- scratch (device globals; no allocation allowed) ----------
__device__ float g_Q[(size_t)BB*HH*SS*DH];   // fragment-permuted Q
__device__ float g_K[(size_t)BB*HH*SS*DH];   // fragment-permuted K
__device__ float g_V[(size_t)BB*HH*SS*DH];   // fragment-permuted V
__device__ float g_ctx[(size_t)ROWS*DM];
__device__ float g_Wt[(size_t)4*DM*DM];      // fragment-permuted weights
__device__ float g_attn_fb[(size_t)BB*HH*SS*SS];
__device__ float g_out_fb[(size_t)ROWS*DM];

// ---------------- helpers ---------------------------------------------------
__device__ __forceinline__ uint32_t smem_u32(const void* p) {
    uint32_t a;
    asm("{ .reg .u64 t; cvta.to.shared.u64 t, %1; cvt.u32.u64 %0, t; }" : "=r"(a) : "l"(p));
    return a;
}
__device__ __forceinline__ float tf32r(float x) {
    uint32_t u;
    asm("cvt.rna.tf32.f32 %0, %1;" : "=r"(u) : "f"(x));
    return __uint_as_float(u);
}
__device__ __forceinline__ void cp16(uint32_t dst, const void* src) {
    asm volatile("cp.async.cg.shared.global [%0], [%1], 16;" :: "r"(dst), "l"(src));
}

#define MMA4(c, a, b0, b1) \
    asm volatile("mma.sync.aligned.m16n8k8.row.col.f32.tf32.tf32.f32 " \
        "{%0,%1,%2,%3},{%4,%5,%6,%7},{%8,%9},{%0,%1,%2,%3};" \
        : "+f"((c)[0]), "+f"((c)[1]), "+f"((c)[2]), "+f"((c)[3]) \
        : "r"((a)[0]), "r"((a)[1]), "r"((a)[2]), "r"((a)[3]), "r"(b0), "r"(b1))

// FMA-pipe exp. Inputs are O(1) or ~-1e9 (masked).
__device__ __forceinline__ float fexp(float x) {
    float y = x * 1.442695040888963f;
    y = fmaxf(y, -126.0f);
    float t = y + 12582912.0f;
    float n = t - 12582912.0f;
    float f = y - n;
    float p = 1.33335581e-3f;
    p = fmaf(p, f, 9.61812911e-3f);
    p = fmaf(p, f, 5.55041087e-2f);
    p = fmaf(p, f, 2.40226507e-1f);
    p = fmaf(p, f, 6.93147180e-1f);
    p = fmaf(p, f, 1.0f);
    float s = __int_as_float(((int)n + 127) << 23);
    return p * s;
}

// ---------------- weight transpose -> fragment-permuted + tf32 round --------
__global__ __launch_bounds__(256) void wt4_kernel(
    const float* __restrict__ w0, const float* __restrict__ w1,
    const float* __restrict__ w2, const float* __restrict__ w3,
    float* __restrict__ Wt)
{
    __shared__ float t[32][33];
    int z = blockIdx.z;
    const float* W = (z == 0) ? w0 : (z == 1) ? w1 : (z == 2) ? w2 : w3;
    float* out = Wt + (size_t)z * DM * DM;
    int tx = threadIdx.x, ty = threadIdx.y;
    int bx = blockIdx.x * 32, by = blockIdx.y * 32;
#pragma unroll
    for (int j = 0; j < 32; j += 8)
        t[ty + j][tx] = W[(size_t)(by + ty + j) * DM + bx + tx];
    __syncthreads();
#pragma unroll
    for (int j = 0; j < 32; j += 8) {
        int n = bx + ty + j, k = by + tx;
        int kki = k >> 3, tt = k & 3, e = (k >> 2) & 1;
        int n8 = n >> 3, g = n & 7;
        out[(size_t)(kki * 96 + n8) * 64 + (g * 4 + tt) * 2 + e] = tf32r(t[tx][ty + j]);
    }
}

// ---------------- projection GEMM via mma.sync tf32 --------------------------
#define PJM 128
#define PJN 128
#define PJK 16
#define ASD 20
#define BSTG 2048
#define NCHK (GK / PJK)        // 48

__device__ __forceinline__ void proj_load(
    int tid, int bm, int bn, int c, const float* X, const float* WP,
    uint32_t abase, uint32_t bbase)
{
    int k0 = c * PJK;
#pragma unroll
    for (int j = 0; j < 2; j++) {
        int i = tid + j * 256;
        int r = i >> 2, c4 = (i & 3) * 4;
        cp16(abase + (uint32_t)(r * ASD + c4) * 4, X + (size_t)(bm + r) * GK + k0 + c4);
    }
    const float* Wc = WP + (size_t)(2 * c * 96 + (bn >> 3)) * 64;
#pragma unroll
    for (int j = 0; j < 2; j++) {
        int i = tid + j * 256;
        int jj = i >> 8;
        int off = (i & 255) * 4;
        cp16(bbase + (uint32_t)(jj * 1024 + off) * 4, Wc + (size_t)jj * 96 * 64 + off);
    }
    asm volatile("cp.async.commit_group;" ::: "memory");
}

__device__ __forceinline__ void proj_body(
    const float* __restrict__ X, const float* __restrict__ WP,
    const float* __restrict__ bias, float* __restrict__ out, int mode)
{
    __shared__ float As[2][PJM * ASD];
    __shared__ float Bs[2][BSTG];
    const int tid = threadIdx.x, warp = tid >> 5, lane = tid & 31;
    const int g = lane >> 2, t = lane & 3;
    const int bm = blockIdx.y * PJM, bn = blockIdx.x * PJN;
    const int m0 = (warp & 3) * 32, n0 = (warp >> 2) * 64;
    const int n8b = (warp >> 2) * 8;

    uint32_t ab[2] = { smem_u32(&As[0][0]), smem_u32(&As[1][0]) };
    uint32_t bb[2] = { smem_u32(&Bs[0][0]), smem_u32(&Bs[1][0]) };

    float cf[2][8][4];
#pragma unroll
    for (int mt = 0; mt < 2; mt++)
#pragma unroll
        for (int nt = 0; nt < 8; nt++)
#pragma unroll
            for (int i = 0; i < 4; i++) cf[mt][nt][i] = 0.f;

    proj_load(tid, bm, bn, 0, X, WP, ab[0], bb[0]);

    for (int c = 0; c < NCHK; c++) {
        int buf = c & 1;
        if (c + 1 < NCHK) {
            proj_load(tid, bm, bn, c + 1, X, WP, ab[buf ^ 1], bb[buf ^ 1]);
            asm volatile("cp.async.wait_group 1;" ::: "memory");
        } else {
            asm volatile("cp.async.wait_group 0;" ::: "memory");
        }
        __syncthreads();
#pragma unroll
        for (int kk = 0; kk < PJK; kk += 8) {
            uint32_t a[2][4];
#pragma unroll
            for (int mt = 0; mt < 2; mt++) {
                const float* ap = &As[buf][(m0 + mt * 16 + g) * ASD + kk + t];
                a[mt][0] = __float_as_uint(tf32r(ap[0]));
                a[mt][1] = __float_as_uint(tf32r(ap[8 * ASD]));
                a[mt][2] = __float_as_uint(tf32r(ap[4]));
                a[mt][3] = __float_as_uint(tf32r(ap[8 * ASD + 4]));
            }
            uint32_t bf[8][2];
#pragma unroll
            for (int nt = 0; nt < 8; nt++) {
                float2 bv = *(float2*)&Bs[buf][((kk >> 3) * 16 + n8b + nt) * 64 + lane * 2];
                bf[nt][0] = __float_as_uint(bv.x);
                bf[nt][1] = __float_as_uint(bv.y);
            }
#pragma unroll
            for (int mt = 0; mt < 2; mt++)
#pragma unroll
                for (int nt = 0; nt < 8; nt++)
                    MMA4(cf[mt][nt], a[mt], bf[nt][0], bf[nt][1]);
        }
        __syncthreads();
    }

#pragma unroll
    for (int mt = 0; mt < 2; mt++) {
        int m_lo = bm + m0 + mt * 16 + g;
#pragma unroll
        for (int nt = 0; nt < 8; nt++) {
            int col = bn + n0 + nt * 8 + 2 * t;
            float b0v = __ldg(bias + col), b1v = __ldg(bias + col + 1);
            float v0 = cf[mt][nt][0] + b0v;
            float v1 = cf[mt][nt][1] + b1v;
            float v2 = cf[mt][nt][2] + b0v;
            float v3 = cf[mt][nt][3] + b1v;
            if (mode == 3) {
                *(float2*)(out + (size_t)m_lo * DM + col)       = make_float2(v0, v1);
                *(float2*)(out + (size_t)(m_lo + 8) * DM + col) = make_float2(v2, v3);
            } else {
                int bdx = m_lo >> 11, s = m_lo & (SS - 1);
                int hh = col / DH, k = col - hh * DH;
                if (mode == 2) {
                    int c2 = s >> 7, tl = s & 127;
                    int kki = tl >> 3, tt = tl & 3, e = (tl >> 2) & 1;
                    int n8 = k >> 3, gg = k & 7;
                    size_t base = (((size_t)bdx * HH + hh) * 16 + c2) * 12288;
                    out[base + (size_t)(kki * 12 + n8) * 64 + (gg * 4 + tt) * 2 + e]             = tf32r(v0);
                    out[base + (size_t)(kki * 12 + n8) * 64 + ((gg + 1) * 4 + tt) * 2 + e]       = tf32r(v1);
                    out[base + (size_t)((kki + 1) * 12 + n8) * 64 + (gg * 4 + tt) * 2 + e]       = tf32r(v2);
                    out[base + (size_t)((kki + 1) * 12 + n8) * 64 + ((gg + 1) * 4 + tt) * 2 + e] = tf32r(v3);
                } else if (mode == 0) {
                    int qt = s >> 6, r = s & 63;
                    int A = (r >> 4) * 12 + (k >> 3);
                    int ln = ((r & 7) << 2) | (k & 3);
                    int e = ((k >> 2) & 1) * 2;
                    size_t base = ((((size_t)bdx * HH + hh) * 32 + qt) * 48 + A) * 128 + ln * 4 + e;
                    *(float2*)(out + base)     = make_float2(tf32r(v0), tf32r(v2));
                    *(float2*)(out + base + 4) = make_float2(tf32r(v1), tf32r(v3));
                } else {
                    int c2 = s >> 7, r = s & 127;
                    int grp = ((r >> 4) & 1) * 48 + (r >> 5) * 12 + (k >> 3);
                    int ln = ((r & 7) << 2) | (k & 3);
                    int e1 = (k >> 2) & 1;
                    size_t base = (((size_t)bdx * HH + hh) * 16 + c2) * 12288 + grp * 128 + ln * 4;
                    out[base + e1]     = tf32r(v0);
                    out[base + 2 + e1] = tf32r(v2);
                    out[base + 4 + e1] = tf32r(v1);
                    out[base + 6 + e1] = tf32r(v3);
                }
            }
        }
    }
}

__global__ __launch_bounds__(256) void proj_qkv(
    const float* __restrict__ q_in, const float* __restrict__ k_in,
    const float* __restrict__ v_in,
    const float* __restrict__ bq, const float* __restrict__ bk,
    const float* __restrict__ bv,
    const float* __restrict__ Wt,
    float* __restrict__ outQ, float* __restrict__ outK, float* __restrict__ outV)
{
    int z = blockIdx.z;
    const float* X = (z == 0) ? q_in : (z == 1) ? k_in : v_in;
    const float* bias = (z == 0) ? bq : (z == 1) ? bk : bv;
    float* out = (z == 0) ? outQ : (z == 1) ? outK : outV;
    proj_body(X, Wt + (size_t)z * DM * DM, bias, out, z);
}

__global__ __launch_bounds__(256) void proj_out(
    const float* __restrict__ X, const float* __restrict__ Wt,
    const float* __restrict__ bias, float* __restrict__ out)
{
    proj_body(X, Wt, bias, out, 3);
}

// ---------------- attention (recompute-QK; single attn write; LDG-V) --------
#define QT 64
#define TK 128
#define NCH (SS / TK)     // 16
#define PEA 132
#define QP_F 6144
#define K_F 12288
#define PE_F (64*PEA)     // 8448
#define ATTN_SMEM ((QP_F + K_F + PE_F + 128 + 256 + 64) * 4)   // 109312

__global__ __launch_bounds__(256, 2) void attn_kernel(
    const float* __restrict__ gQ, const float* __restrict__ gK,
    const float* __restrict__ gV, const float* __restrict__ mask,
    float* __restrict__ attn, float* __restrict__ ctx)
{
    extern __shared__ float sm[];
    float* QP   = sm;
    float* KP0  = sm + QP_F;
    float* KP1  = KP0 + 6144;
    float* pe   = sm + QP_F + K_F;
    float* ms   = pe + PE_F;               // [128]
    float* red  = ms + 128;                // [4][64]
    float* invs = red + 256;               // [64]

    const int tid = threadIdx.x;
    const int warp = tid >> 5, lane = tid & 31;
    const int g = lane >> 2, t = lane & 3;
    const int wm = warp & 1, wn = warp >> 1;          // 2(m) x 4(n)
    const int qt = blockIdx.x, h = blockIdx.y, b = blockIdx.z;

    const float* Qp = gQ + (((size_t)b * HH + h) * 32 + qt) * 6144;
    const float* Kb = gK + ((size_t)b * HH + h) * 16 * 12288;
    const float* Vb = gV + ((size_t)b * HH + h) * 16 * 12288;
    float* Ab = attn + (((size_t)b * HH + h) * SS + (size_t)qt * QT) * (size_t)SS;

    const uint32_t qpb = smem_u32(QP);
    const uint32_t kpb = smem_u32(KP0);

    // Q fill: linear coalesced cp.async (24 KB once)
#pragma unroll
    for (int l = 0; l < 6; l++) {
        int i = tid + l * 256;
        cp16(qpb + (uint32_t)i * 16, Qp + i * 4);
    }
    asm volatile("cp.async.commit_group;" ::: "memory");

    const float SCALE = rsqrtf((float)DH);
    float sumr[4] = {0.f, 0.f, 0.f, 0.f};

    // ================= PASS 1: QK + exp + row sums (no stores) ==============
    for (int c = 0; c < NCH; c++) {
        __syncthreads();
        const float* Kc = Kb + (size_t)c * 12288;
#pragma unroll
        for (int l = 0; l < 12; l++) {
            int i = tid + l * 256;
            cp16(kpb + (uint32_t)i * 16, Kc + i * 4);
        }
        asm volatile("cp.async.commit_group;" ::: "memory");
        if (tid < TK) ms[tid] = mask[(size_t)b * SS + c * TK + tid] * -1e9f;
        asm volatile("cp.async.wait_group 0;" ::: "memory");
        __syncthreads();

        float cf[2][4][4];
#pragma unroll
        for (int mt = 0; mt < 2; mt++)
#pragma unroll
            for (int nt = 0; nt < 4; nt++)
#pragma unroll
                for (int i = 0; i < 4; i++) cf[mt][nt][i] = 0.f;

#pragma unroll
        for (int kki = 0; kki < 12; kki++) {
            float4 q0 = *(float4*)&QP[((wm * 2 + 0) * 12 + kki) * 128 + lane * 4];
            float4 q1 = *(float4*)&QP[((wm * 2 + 1) * 12 + kki) * 128 + lane * 4];
            float4 k0 = *(float4*)&KP0[(wn * 12 + kki) * 128 + lane * 4];
            float4 k1 = *(float4*)&KP1[(wn * 12 + kki) * 128 + lane * 4];
            uint32_t a0[4] = {__float_as_uint(q0.x), __float_as_uint(q0.y),
                              __float_as_uint(q0.z), __float_as_uint(q0.w)};
            uint32_t a1[4] = {__float_as_uint(q1.x), __float_as_uint(q1.y),
                              __float_as_uint(q1.z), __float_as_uint(q1.w)};
            MMA4(cf[0][0], a0, __float_as_uint(k0.x), __float_as_uint(k0.y));
            MMA4(cf[0][1], a0, __float_as_uint(k0.z), __float_as_uint(k0.w));
            MMA4(cf[0][2], a0, __float_as_uint(k1.x), __float_as_uint(k1.y));
            MMA4(cf[0][3], a0, __float_as_uint(k1.z), __float_as_uint(k1.w));
            MMA4(cf[1][0], a1, __float_as_uint(k0.x), __float_as_uint(k0.y));
            MMA4(cf[1][1], a1, __float_as_uint(k0.z), __float_as_uint(k0.w));
            MMA4(cf[1][2], a1, __float_as_uint(k1.x), __float_as_uint(k1.y));
            MMA4(cf[1][3], a1, __float_as_uint(k1.z), __float_as_uint(k1.w));
        }

#pragma unroll
        for (int mt = 0; mt < 2; mt++)
#pragma unroll
            for (int nt = 0; nt < 4; nt++) {
                int lc = wn * 32 + nt * 8 + 2 * t;
                float m0 = ms[lc], m1 = ms[lc + 1];
                float e00 = fexp(cf[mt][nt][0] * SCALE + m0);
                float e01 = fexp(cf[mt][nt][1] * SCALE + m1);
                float e10 = fexp(cf[mt][nt][2] * SCALE + m0);
                float e11 = fexp(cf[mt][nt][3] * SCALE + m1);
                sumr[mt * 2 + 0] += e00 + e01;
                sumr[mt * 2 + 1] += e10 + e11;
            }
    }
    // reduce over t (quad), then over the 4 n-warps via smem
#pragma unroll
    for (int j = 0; j < 4; j++) {
        sumr[j] += __shfl_xor_sync(0xffffffffu, sumr[j], 1);
        sumr[j] += __shfl_xor_sync(0xffffffffu, sumr[j], 2);
    }
    if (t == 0) {
#pragma unroll
        for (int j = 0; j < 4; j++) {
            int row = wm * 32 + (j >> 1) * 16 + (j & 1) * 8 + g;
            red[wn * 64 + row] = sumr[j];
        }
    }
    __syncthreads();
    if (tid < 64) {
        float s = red[tid] + red[64 + tid] + red[128 + tid] + red[192 + tid];
        invs[tid] = 1.0f / s;
    }
    __syncthreads();

    // per-thread inverse row-sums (rows wm*32 + mt*16 + hf*8 + g)
    float inv[2][2];
    inv[0][0] = invs[wm * 32 + g];
    inv[0][1] = invs[wm * 32 + 8 + g];
    inv[1][0] = invs[wm * 32 + 16 + g];
    inv[1][1] = invs[wm * 32 + 24 + g];

    // ===== PASS 2: recompute QK, normalize+write attn, stage pe, PV =========
    float cx[2][3][4];
#pragma unroll
    for (int mt = 0; mt < 2; mt++)
#pragma unroll
        for (int nt = 0; nt < 3; nt++)
#pragma unroll
            for (int i = 0; i < 4; i++) cx[mt][nt][i] = 0.f;

    // prefetch K(0)
    __syncthreads();
#pragma unroll
    for (int l = 0; l < 12; l++) {
        int i = tid + l * 256;
        cp16(kpb + (uint32_t)i * 16, Kb + i * 4);
    }
    asm volatile("cp.async.commit_group;" ::: "memory");

    for (int c = 0; c < NCH; c++) {
        if (tid < TK) ms[tid] = mask[(size_t)b * SS + c * TK + tid] * -1e9f;
        asm volatile("cp.async.wait_group 0;" ::: "memory");
        __syncthreads();

        float cf[2][4][4];
#pragma unroll
        for (int mt = 0; mt < 2; mt++)
#pragma unroll
            for (int nt = 0; nt < 4; nt++)
#pragma unroll
                for (int i = 0; i < 4; i++) cf[mt][nt][i] = 0.f;

#pragma unroll
        for (int kki = 0; kki < 12; kki++) {
            float4 q0 = *(float4*)&QP[((wm * 2 + 0) * 12 + kki) * 128 + lane * 4];
            float4 q1 = *(float4*)&QP[((wm * 2 + 1) * 12 + kki) * 128 + lane * 4];
            float4 k0 = *(float4*)&KP0[(wn * 12 + kki) * 128 + lane * 4];
            float4 k1 = *(float4*)&KP1[(wn * 12 + kki) * 128 + lane * 4];
            uint32_t a0[4] = {__float_as_uint(q0.x), __float_as_uint(q0.y),
                              __float_as_uint(q0.z), __float_as_uint(q0.w)};
            uint32_t a1[4] = {__float_as_uint(q1.x), __float_as_uint(q1.y),
                              __float_as_uint(q1.z), __float_as_uint(q1.w)};
            MMA4(cf[0][0], a0, __float_as_uint(k0.x), __float_as_uint(k0.y));
            MMA4(cf[0][1], a0, __float_as_uint(k0.z), __float_as_uint(k0.w));
            MMA4(cf[0][2], a0, __float_as_uint(k1.x), __float_as_uint(k1.y));
            MMA4(cf[0][3], a0, __float_as_uint(k1.z), __float_as_uint(k1.w));
            MMA4(cf[1][0], a1, __float_as_uint(k0.x), __float_as_uint(k0.y));
            MMA4(cf[1][1], a1, __float_as_uint(k0.z), __float_as_uint(k0.w));
            MMA4(cf[1][2], a1, __float_as_uint(k1.x), __float_as_uint(k1.y));
            MMA4(cf[1][3], a1, __float_as_uint(k1.z), __float_as_uint(k1.w));
        }

        // epilogue: e = exp(logit)*inv -> final attn write + permuted pe stage
#pragma unroll
        for (int mt = 0; mt < 2; mt++)
#pragma unroll
            for (int nt = 0; nt < 4; nt++) {
                int lc = wn * 32 + nt * 8 + 2 * t;
                float m0 = ms[lc], m1 = ms[lc + 1];
                int gc = c * TK + lc;
                float e00 = fexp(cf[mt][nt][0] * SCALE + m0) * inv[mt][0];
                float e01 = fexp(cf[mt][nt][1] * SCALE + m1) * inv[mt][0];
                float e10 = fexp(cf[mt][nt][2] * SCALE + m0) * inv[mt][1];
                float e11 = fexp(cf[mt][nt][3] * SCALE + m1) * inv[mt][1];
                int r0 = wm * 32 + mt * 16 + g;
                *(float2*)(Ab + (size_t)r0 * SS + gc)       = make_float2(e00, e01);
                *(float2*)(Ab + (size_t)(r0 + 8) * SS + gc) = make_float2(e10, e11);
                // pe permuted: group (wm*2+mt, c8 = wn*4+nt), lane (g*4 + col&3), j = hf + 2*((col>>2)&1)
                int G = ((wm * 2 + mt) * 16 + wn * 4 + nt) * PEA;
                int t0 = lc & 3, ke0 = (lc >> 2) & 1;
                float* pb0 = &pe[G + (g * 4 + t0) * 4 + 2 * ke0];
                pb0[0] = tf32r(e00);
                pb0[1] = tf32r(e10);
                float* pb1 = &pe[G + (g * 4 + t0 + 1) * 4 + 2 * ke0];
                pb1[0] = tf32r(e01);
                pb1[1] = tf32r(e11);
            }
        __syncthreads();

        // prefetch K(c+1) (overlaps PV)
        if (c + 1 < NCH) {
            const float* Kn = Kb + (size_t)(c + 1) * 12288;
#pragma unroll
            for (int l = 0; l < 12; l++) {
                int i = tid + l * 256;
                cp16(kpb + (uint32_t)i * 16, Kn + i * 4);
            }
            asm volatile("cp.async.commit_group;" ::: "memory");
        }

        // PV: ctx += P @ V; a from pe (LDS.128), b from gmem permuted V (LDG.64)
        const float* Vc = Vb + (size_t)c * 12288;
#pragma unroll 4
        for (int kki = 0; kki < 16; kki++) {
            uint32_t a[2][4];
#pragma unroll
            for (int mt = 0; mt < 2; mt++) {
                float4 av = *(float4*)&pe[((wm * 2 + mt) * 16 + kki) * PEA + lane * 4];
                a[mt][0] = __float_as_uint(av.x);
                a[mt][1] = __float_as_uint(av.y);
                a[mt][2] = __float_as_uint(av.z);
                a[mt][3] = __float_as_uint(av.w);
            }
#pragma unroll
            for (int nt = 0; nt < 3; nt++) {
                float2 bv = __ldg((const float2*)(Vc + (kki * 12 + wn * 3 + nt) * 64 + lane * 2));
                uint32_t b0 = __float_as_uint(bv.x);
                uint32_t b1 = __float_as_uint(bv.y);
#pragma unroll
                for (int mt = 0; mt < 2; mt++)
                    MMA4(cx[mt][nt], a[mt], b0, b1);
            }
        }
        __syncthreads();   // all warps done with pe before next epilogue rewrites it
    }

    // ctx write ([B,S,D] concat-head layout), tf32-rounded for the O-projection
#pragma unroll
    for (int mt = 0; mt < 2; mt++)
#pragma unroll
        for (int nt = 0; nt < 3; nt++) {
            int col = h * DH + wn * 24 + nt * 8 + 2 * t;
#pragma unroll
            for (int hf = 0; hf < 2; hf++) {
                int r = wm * 32 + mt * 16 + hf * 8 + g;
                float2 o = make_float2(tf32r(cx[mt][nt][hf * 2]),
                                       tf32r(cx[mt][nt][hf * 2 + 1]));
                *(float2*)(ctx + ((size_t)b * SS + qt * QT + r) * DM + col) = o;
            }
        }
}

// ---------------- launch ----------------------------------------------------
static float* symaddr(const void* sym) {
    void* p = 0;
    cudaGetSymbolAddress(&p, sym);
    return (float*)p;
}

extern "C" void kernel_launch(void* const* d_in, const int* in_sizes, int n_in,
                              void* d_out, int out_size)
{
    const float* q_in = (const float*)d_in[0];
    const float* k_in = (const float*)d_in[1];
    const float* v_in = (const float*)d_in[2];
    const float* mask = (const float*)d_in[3];
    const float* wq = (const float*)d_in[4];
    const float* bq = (const float*)d_in[5];
    const float* wk = (const float*)d_in[6];
    const float* bk = (const float*)d_in[7];
    const float* wv = (const float*)d_in[8];
    const float* bv = (const float*)d_in[9];
    const float* wo = (const float*)d_in[10];
    const float* bo = (const float*)d_in[11];

    float* pQ   = symaddr(g_Q);
    float* pK   = symaddr(g_K);
    float* pV   = symaddr(g_V);
    float* pctx = symaddr(g_ctx);
    float* pWt  = symaddr(g_Wt);

    const long long OUT_E = (long long)ROWS * DM;
    const long long ATT_E = (long long)BB * HH * SS * (long long)SS;

    float* outp  = (float*)d_out;
    float* attnp;
    if ((long long)out_size >= OUT_E + ATT_E) {
        attnp = (float*)d_out + OUT_E;
    } else if ((long long)out_size == ATT_E) {
        attnp = (float*)d_out;
        outp  = symaddr(g_out_fb);
    } else {
        attnp = symaddr(g_attn_fb);
    }

    static bool attr_done = false;
    if (!attr_done) {
        cudaFuncSetAttribute(attn_kernel, cudaFuncAttributeMaxDynamicSharedMemorySize, ATTN_SMEM);
        attr_done = true;
    }

    // 1) weights -> fragment-permuted + tf32 (one launch)
    wt4_kernel<<<dim3(DM / 32, DM / 32, 4), dim3(32, 8)>>>(wq, wk, wv, wo, pWt);

    // 2) fused Q/K/V projections; epilogues write Q/K/V fragment-permuted
    proj_qkv<<<dim3(DM / PJN, ROWS / PJM, 3), 256>>>(
        q_in, k_in, v_in, bq, bk, bv, pWt, pQ, pK, pV);

    // 3) attention (recompute-QK two-pass; single final attn write; LDG-V PV)
    attn_kernel<<<dim3(SS / QT, HH, BB), 256, ATTN_SMEM>>>(pQ, pK, pV, mask, attnp, pctx);

    // 4) output projection
    proj_out<<<dim3(DM / PJN, ROWS / PJM), 256>>>(pctx, pWt + 3 * (size_t)DM * DM, bo, outp);
}

// round 16
// speedup vs baseline: 2.0475x; 1.5837x over previous
#include <cuda_runtime.h>
#include <cuda_fp16.h>
#include <cstdint>
#include <math.h>

#define BB 4
#define HH 8
#define SS 2048
#define DM 768
#define DH 96
#define ROWS (BB*SS)          // 8192
#define GK DM                 // 768

// ---------------- scratch (device globals; no allocation allowed) ----------
__device__ __half g_Xp[(size_t)3*ROWS*DM];        // permuted fp16 inputs (A-frag)
__device__ __half g_Qp[(size_t)BB*HH*SS*DH];      // permuted fp16 Q (A-frag, qt64 tiles)
__device__ __half g_Kp[(size_t)BB*HH*SS*DH];      // permuted fp16 K (B-frag, c128 tiles)
__device__ __half g_Vp[(size_t)BB*HH*SS*DH];      // permuted fp16 V (B-frag, c128 tiles)
__device__ __half g_ctxp[(size_t)ROWS*DM];        // permuted fp16 ctx (A-frag)
__device__ __half g_Wp[(size_t)4*DM*DM];          // permuted fp16 weights (B-frag)
__device__ float g_attn_fb[(size_t)BB*HH*SS*SS];
__device__ float g_out_fb[(size_t)ROWS*DM];

// ---------------- helpers ---------------------------------------------------
__device__ __forceinline__ uint32_t smem_u32(const void* p) {
    uint32_t a;
    asm("{ .reg .u64 t; cvta.to.shared.u64 t, %1; cvt.u32.u64 %0, t; }" : "=r"(a) : "l"(p));
    return a;
}
__device__ __forceinline__ void cp16(uint32_t dst, const void* src) {
    asm volatile("cp.async.cg.shared.global [%0], [%1], 16;" :: "r"(dst), "l"(src));
}
__device__ __forceinline__ uint32_t ph2(float lo, float hi) {
    __half2 h = __floats2half2_rn(lo, hi);
    return *reinterpret_cast<uint32_t*>(&h);
}

// fp16 mma m16n8k16, fp32 accumulate (baseline PTX, sm_70+)
#define MMAH(c, a, b0, b1) \
    asm volatile("mma.sync.aligned.m16n8k16.row.col.f32.f16.f16.f32 " \
        "{%0,%1,%2,%3},{%4,%5,%6,%7},{%8,%9},{%0,%1,%2,%3};" \
        : "+f"((c)[0]), "+f"((c)[1]), "+f"((c)[2]), "+f"((c)[3]) \
        : "r"((a)[0]), "r"((a)[1]), "r"((a)[2]), "r"((a)[3]), "r"(b0), "r"(b1))

// FMA-pipe exp. Inputs are O(1) or ~-1e9 (masked).
__device__ __forceinline__ float fexp(float x) {
    float y = x * 1.442695040888963f;
    y = fmaxf(y, -126.0f);
    float t = y + 12582912.0f;
    float n = t - 12582912.0f;
    float f = y - n;
    float p = 1.33335581e-3f;
    p = fmaf(p, f, 9.61812911e-3f);
    p = fmaf(p, f, 5.55041087e-2f);
    p = fmaf(p, f, 2.40226507e-1f);
    p = fmaf(p, f, 6.93147180e-1f);
    p = fmaf(p, f, 1.0f);
    float s = __int_as_float(((int)n + 127) << 23);
    return p * s;
}

// ---------------- weights -> fp16 B-frag permuted ----------------------------
// Wp[((kki*96 + n8)*32 + gt*4+tt)*4 + bsel*2 + {lo,hi}] = fp16(W[k][n]) pairs (k,k+1)
__global__ __launch_bounds__(256) void wt4_kernel(
    const float* __restrict__ w0, const float* __restrict__ w1,
    const float* __restrict__ w2, const float* __restrict__ w3,
    __half* __restrict__ Wp)
{
    __shared__ float t[32][33];
    int z = blockIdx.z;
    const float* W = (z == 0) ? w0 : (z == 1) ? w1 : (z == 2) ? w2 : w3;
    __half* out = Wp + (size_t)z * DM * DM;
    int tx = threadIdx.x, ty = threadIdx.y;             // 32 x 8
    int bx = blockIdx.x * 32, by = blockIdx.y * 32;     // bx: n, by: k
#pragma unroll
    for (int j = 0; j < 32; j += 8)
        t[ty + j][tx] = W[(size_t)(by + ty + j) * DM + bx + tx];   // t[kr][nc]
    __syncthreads();
    int tid = ty * 32 + tx;
#pragma unroll
    for (int l = 0; l < 2; l++) {
        int pi = tid + l * 256;          // 0..511
        int kp = pi & 15, nl = pi >> 4;  // k-pair, n-local
        float lo = t[2 * kp][nl], hi = t[2 * kp + 1][nl];
        int k = by + 2 * kp, n = bx + nl;
        int kki = k >> 4, tt = (k & 7) >> 1, bsel = (k >> 3) & 1;
        int n8 = n >> 3, gt = n & 7;
        *(uint32_t*)(out + ((size_t)(kki * 96 + n8) * 32 + gt * 4 + tt) * 4 + bsel * 2) = ph2(lo, hi);
    }
}

// ---------------- inputs -> fp16 A-frag permuted -----------------------------
// Xp[((mt*48+kki)*32 + g*4+tt)*8 + j*2 + {lo,hi}], j = hf + 2*kh
__global__ __launch_bounds__(256) void xcvt_kernel(
    const float* __restrict__ q, const float* __restrict__ k,
    const float* __restrict__ v, __half* __restrict__ Xp)
{
    int z = blockIdx.y;
    const float* X = (z == 0) ? q : (z == 1) ? k : v;
    __half* out = Xp + (size_t)z * ROWS * DM;
    int pid = blockIdx.x * 256 + threadIdx.x;     // ROWS*384 total
    int m = pid / (DM / 2), kp = pid % (DM / 2);
    float2 xv = *(const float2*)(X + (size_t)m * DM + 2 * kp);
    int kk = 2 * kp;
    int mt = m >> 4, g = m & 7, hf = (m >> 3) & 1;
    int kki = kk >> 4, tt = (kk & 7) >> 1, kh = (kk >> 3) & 1;
    int j = hf + 2 * kh;
    *(uint32_t*)(out + ((size_t)(mt * 48 + kki) * 32 + g * 4 + tt) * 8 + j * 2) = ph2(xv.x, xv.y);
}

// ---------------- projection GEMM via mma.sync fp16 --------------------------
// Tile 128x128, K-chunk 32 (2 kki), 2-stage cp.async, all-fp16 smem.
#define NCHK2 24

__device__ __forceinline__ void proj_load(
    int tid, int mtg0, int bn8, int c, const __half* XP, const __half* WP,
    uint32_t abase, uint32_t bbase)
{
    // A: 16 groups (8 m16 x 2 kki) x 512B
#pragma unroll
    for (int l = 0; l < 2; l++) {
        int i = tid + l * 256;
        int gi = i >> 6, ki = (i >> 5) & 1, ln = i & 31;
        cp16(abase + (uint32_t)(((gi * 2 + ki) * 32 + ln) * 16),
             XP + ((size_t)((mtg0 + gi) * 48 + 2 * c + ki)) * 256 + ln * 8);
    }
    // B: 32 groups (2 kki x 16 n8) x 256B
#pragma unroll
    for (int l = 0; l < 2; l++) {
        int i = tid + l * 256;
        int kib = i >> 8, rest = i & 255;
        int n8i = rest >> 4, part = rest & 15;
        cp16(bbase + (uint32_t)(((kib * 16 + n8i) * 16 + part) * 16),
             WP + ((size_t)((2 * c + kib) * 96 + bn8 + n8i)) * 128 + part * 8);
    }
    asm volatile("cp.async.commit_group;" ::: "memory");
}

__device__ __forceinline__ void proj_body(
    const __half* __restrict__ XP, const __half* __restrict__ WP,
    const float* __restrict__ bias, void* __restrict__ outv, int mode)
{
    __shared__ __align__(16) uint32_t As[2][2048];
    __shared__ __align__(16) uint32_t Bs[2][2048];
    const int tid = threadIdx.x, warp = tid >> 5, lane = tid & 31;
    const int g = lane >> 2, t = lane & 3;
    const int bm = blockIdx.y * 128, bn = blockIdx.x * 128;
    const int mtg0 = bm >> 4, bn8 = bn >> 3;
    const int wm4 = warp & 3, wn2 = warp >> 2;

    uint32_t ab[2] = { smem_u32(As[0]), smem_u32(As[1]) };
    uint32_t bb[2] = { smem_u32(Bs[0]), smem_u32(Bs[1]) };

    float cf[2][8][4];
#pragma unroll
    for (int mt = 0; mt < 2; mt++)
#pragma unroll
        for (int nt = 0; nt < 8; nt++)
#pragma unroll
            for (int i = 0; i < 4; i++) cf[mt][nt][i] = 0.f;

    proj_load(tid, mtg0, bn8, 0, XP, WP, ab[0], bb[0]);

    for (int c = 0; c < NCHK2; c++) {
        int buf = c & 1;
        if (c + 1 < NCHK2) {
            proj_load(tid, mtg0, bn8, c + 1, XP, WP, ab[buf ^ 1], bb[buf ^ 1]);
            asm volatile("cp.async.wait_group 1;" ::: "memory");
        } else {
            asm volatile("cp.async.wait_group 0;" ::: "memory");
        }
        __syncthreads();
#pragma unroll
        for (int ki = 0; ki < 2; ki++) {
            uint32_t a[2][4];
#pragma unroll
            for (int mt = 0; mt < 2; mt++) {
                uint4 av = *(uint4*)&As[buf][(((wm4 * 2 + mt) * 2 + ki) * 32 + lane) * 4];
                a[mt][0] = av.x; a[mt][1] = av.y; a[mt][2] = av.z; a[mt][3] = av.w;
            }
            uint32_t bf[8][2];
#pragma unroll
            for (int nt = 0; nt < 8; nt++) {
                uint2 bv = *(uint2*)&Bs[buf][((ki * 16 + wn2 * 8 + nt) * 32 + lane) * 2];
                bf[nt][0] = bv.x; bf[nt][1] = bv.y;
            }
#pragma unroll
            for (int mt = 0; mt < 2; mt++)
#pragma unroll
                for (int nt = 0; nt < 8; nt++)
                    MMAH(cf[mt][nt], a[mt], bf[nt][0], bf[nt][1]);
        }
        __syncthreads();
    }

    // epilogue
#pragma unroll
    for (int mt = 0; mt < 2; mt++) {
        int m_lo = bm + wm4 * 32 + mt * 16 + g;
#pragma unroll
        for (int nt = 0; nt < 8; nt++) {
            int col = bn + wn2 * 64 + nt * 8 + 2 * t;
            float b0v = __ldg(bias + col), b1v = __ldg(bias + col + 1);
            float v0 = cf[mt][nt][0] + b0v;   // (m_lo,   col)
            float v1 = cf[mt][nt][1] + b1v;   // (m_lo,   col+1)
            float v2 = cf[mt][nt][2] + b0v;   // (m_lo+8, col)
            float v3 = cf[mt][nt][3] + b1v;   // (m_lo+8, col+1)
            if (mode == 3) {
                float* out = (float*)outv;
                *(float2*)(out + (size_t)m_lo * DM + col)       = make_float2(v0, v1);
                *(float2*)(out + (size_t)(m_lo + 8) * DM + col) = make_float2(v2, v3);
            } else {
                __half* out = (__half*)outv;
                int bdx = m_lo >> 11, s = m_lo & (SS - 1);
                int hh = col / DH, kf = col - hh * DH;
                if (mode == 0) {
                    // Q A-frag permuted per qt64 tile
                    int qt = s >> 6, r = s & 63;
                    int A = (r >> 4) * 6 + (kf >> 4);
                    int kh = (kf >> 3) & 1;
                    int ln = ((r & 7) << 2) | ((kf & 7) >> 1);
                    __half* dst = out + ((((size_t)(bdx * HH + hh) * 32 + qt) * 24 + A) * 32 + ln) * 8 + kh * 4;
                    *(uint2*)dst = make_uint2(ph2(v0, v1), ph2(v2, v3));
                } else if (mode == 1) {
                    // K B-frag permuted per c128 tile (pairs along feature k)
                    int c2 = s >> 7, n = s & 127;
                    int grp = (n >> 3) * 6 + (kf >> 4);
                    int ln = ((n & 7) << 2) | ((kf & 7) >> 1);
                    int bsel = (kf >> 3) & 1;
                    __half* base = out + ((((size_t)(bdx * HH + hh) * 16 + c2) * 96 + grp) * 32 + ln) * 4 + bsel * 2;
                    *(uint32_t*)base          = ph2(v0, v1);
                    *(uint32_t*)(base + 768)  = ph2(v2, v3);   // n+8 -> grp+6
                } else {
                    // V B-frag permuted (pairs along seq k) -> lane exchange
                    int c2 = s >> 7, k = s & 127, n = kf;
                    float s0 = __shfl_xor_sync(0xffffffffu, v0, 4);
                    float s1 = __shfl_xor_sync(0xffffffffu, v1, 4);
                    float s2 = __shfl_xor_sync(0xffffffffu, v2, 4);
                    float s3 = __shfl_xor_sync(0xffffffffu, v3, 4);
                    size_t cb = ((size_t)(bdx * HH + hh) * 16 + c2) * 96;
                    if ((k & 1) == 0) {
                        int kp = k;
                        int kki = kp >> 4, tt = (kp & 7) >> 1, bsel = (kp >> 3) & 1;
                        int ln = ((n & 7) << 2) | tt;
                        __half* base = out + ((cb + kki * 12 + (n >> 3)) * 32 + ln) * 4 + bsel * 2;
                        *(uint32_t*)base        = ph2(v0, s0);
                        *(uint32_t*)(base + 16) = ph2(v1, s1);   // n+1 -> ln+4
                    } else {
                        int kp = k + 7;
                        int kki = kp >> 4, tt = (kp & 7) >> 1, bsel = (kp >> 3) & 1;
                        int ln = ((n & 7) << 2) | tt;
                        __half* base = out + ((cb + kki * 12 + (n >> 3)) * 32 + ln) * 4 + bsel * 2;
                        *(uint32_t*)base        = ph2(s2, v2);
                        *(uint32_t*)(base + 16) = ph2(s3, v3);
                    }
                }
            }
        }
    }
}

__global__ __launch_bounds__(256) void proj_qkv(
    const __half* __restrict__ Xp,
    const float* __restrict__ bq, const float* __restrict__ bk,
    const float* __restrict__ bv,
    const __half* __restrict__ Wp,
    __half* __restrict__ outQ, __half* __restrict__ outK, __half* __restrict__ outV)
{
    int z = blockIdx.z;
    const float* bias = (z == 0) ? bq : (z == 1) ? bk : bv;
    void* out = (z == 0) ? (void*)outQ : (z == 1) ? (void*)outK : (void*)outV;
    proj_body(Xp + (size_t)z * ROWS * DM, Wp + (size_t)z * DM * DM, bias, out, z);
}

__global__ __launch_bounds__(256) void proj_out(
    const __half* __restrict__ XP, const __half* __restrict__ Wp,
    const float* __restrict__ bias, float* __restrict__ out)
{
    proj_body(XP, Wp, bias, out, 3);
}

// ---------------- attention (fp16 frags; recompute-QK 2-pass) ----------------
#define QT 64
#define TK 128
#define NCH (SS / TK)     // 16
#define QP_B 12288
#define KP_B 24576
#define PE_B 16384
#define ATTN_SMEM (QP_B + KP_B + PE_B + (128 + 256 + 64) * 4)   // 55040

__global__ __launch_bounds__(256, 2) void attn_kernel(
    const __half* __restrict__ gQ, const __half* __restrict__ gK,
    const __half* __restrict__ gV, const float* __restrict__ mask,
    float* __restrict__ attn, __half* __restrict__ ctxp)
{
    extern __shared__ char smraw[];
    char* QPp = smraw;
    char* KPp = smraw + QP_B;
    char* PEp = smraw + QP_B + KP_B;
    float* ms   = (float*)(smraw + QP_B + KP_B + PE_B);   // [128]
    float* red  = ms + 128;                               // [4][64]
    float* invs = red + 256;                              // [64]

    const int tid = threadIdx.x;
    const int warp = tid >> 5, lane = tid & 31;
    const int g = lane >> 2, t = lane & 3;
    const int wm = warp & 1, wn = warp >> 1;          // 2(m) x 4(n)
    const int qt = blockIdx.x, h = blockIdx.y, b = blockIdx.z;

    const __half* Qp = gQ + ((size_t)((b * HH + h) * 32 + qt)) * 6144;
    const __half* Kb = gK + ((size_t)(b * HH + h)) * 16 * 12288;
    const __half* Vb = gV + ((size_t)(b * HH + h)) * 16 * 12288;
    float* Ab = attn + (((size_t)b * HH + h) * SS + (size_t)qt * QT) * (size_t)SS;

    const uint32_t qpb = smem_u32(QPp);
    const uint32_t kpb = smem_u32(KPp);

    // Q fill (12 KB once, linear)
#pragma unroll
    for (int l = 0; l < 3; l++) {
        int i = tid + l * 256;
        cp16(qpb + (uint32_t)i * 16, Qp + i * 8);
    }
    asm volatile("cp.async.commit_group;" ::: "memory");

    const float SCALE = rsqrtf((float)DH);
    float sumr[4] = {0.f, 0.f, 0.f, 0.f};

    // ================= PASS 1: QK + exp + row sums ==========================
    for (int c = 0; c < NCH; c++) {
        __syncthreads();
        const __half* Kc = Kb + (size_t)c * 12288;
#pragma unroll
        for (int l = 0; l < 6; l++) {
            int i = tid + l * 256;
            cp16(kpb + (uint32_t)i * 16, Kc + i * 8);
        }
        asm volatile("cp.async.commit_group;" ::: "memory");
        if (tid < TK) ms[tid] = mask[(size_t)b * SS + c * TK + tid] * -1e9f;
        asm volatile("cp.async.wait_group 0;" ::: "memory");
        __syncthreads();

        float cf[2][4][4];
#pragma unroll
        for (int mt = 0; mt < 2; mt++)
#pragma unroll
            for (int nt = 0; nt < 4; nt++)
#pragma unroll
                for (int i = 0; i < 4; i++) cf[mt][nt][i] = 0.f;

#pragma unroll
        for (int kki = 0; kki < 6; kki++) {
            uint32_t a[2][4];
#pragma unroll
            for (int mt = 0; mt < 2; mt++) {
                uint4 av = *(const uint4*)(QPp + (((wm * 2 + mt) * 6 + kki) * 32 + lane) * 16);
                a[mt][0] = av.x; a[mt][1] = av.y; a[mt][2] = av.z; a[mt][3] = av.w;
            }
#pragma unroll
            for (int nt = 0; nt < 4; nt++) {
                uint2 bv = *(const uint2*)(KPp + (((wn * 4 + nt) * 6 + kki) * 32 + lane) * 8);
#pragma unroll
                for (int mt = 0; mt < 2; mt++)
                    MMAH(cf[mt][nt], a[mt], bv.x, bv.y);
            }
        }

#pragma unroll
        for (int mt = 0; mt < 2; mt++)
#pragma unroll
            for (int nt = 0; nt < 4; nt++) {
                int lc = wn * 32 + nt * 8 + 2 * t;
                float m0 = ms[lc], m1 = ms[lc + 1];
                float e00 = fexp(cf[mt][nt][0] * SCALE + m0);
                float e01 = fexp(cf[mt][nt][1] * SCALE + m1);
                float e10 = fexp(cf[mt][nt][2] * SCALE + m0);
                float e11 = fexp(cf[mt][nt][3] * SCALE + m1);
                sumr[mt * 2 + 0] += e00 + e01;
                sumr[mt * 2 + 1] += e10 + e11;
            }
    }
#pragma unroll
    for (int j = 0; j < 4; j++) {
        sumr[j] += __shfl_xor_sync(0xffffffffu, sumr[j], 1);
        sumr[j] += __shfl_xor_sync(0xffffffffu, sumr[j], 2);
    }
    if (t == 0) {
#pragma unroll
        for (int j = 0; j < 4; j++) {
            int row = wm * 32 + (j >> 1) * 16 + (j & 1) * 8 + g;
            red[wn * 64 + row] = sumr[j];
        }
    }
    __syncthreads();
    if (tid < 64) {
        float s = red[tid] + red[64 + tid] + red[128 + tid] + red[192 + tid];
        invs[tid] = 1.0f / s;
    }
    __syncthreads();

    float inv[2][2];
    inv[0][0] = invs[wm * 32 + g];
    inv[0][1] = invs[wm * 32 + 8 + g];
    inv[1][0] = invs[wm * 32 + 16 + g];
    inv[1][1] = invs[wm * 32 + 24 + g];

    // ===== PASS 2: recompute QK, write attn, stage pe (fp16), PV ============
    float cx[2][3][4];
#pragma unroll
    for (int mt = 0; mt < 2; mt++)
#pragma unroll
        for (int nt = 0; nt < 3; nt++)
#pragma unroll
            for (int i = 0; i < 4; i++) cx[mt][nt][i] = 0.f;

    __syncthreads();
#pragma unroll
    for (int l = 0; l < 6; l++) {
        int i = tid + l * 256;
        cp16(kpb + (uint32_t)i * 16, Kb + i * 8);
    }
    asm volatile("cp.async.commit_group;" ::: "memory");

    for (int c = 0; c < NCH; c++) {
        if (tid < TK) ms[tid] = mask[(size_t)b * SS + c * TK + tid] * -1e9f;
        asm volatile("cp.async.wait_group 0;" ::: "memory");
        __syncthreads();

        float cf[2][4][4];
#pragma unroll
        for (int mt = 0; mt < 2; mt++)
#pragma unroll
            for (int nt = 0; nt < 4; nt++)
#pragma unroll
                for (int i = 0; i < 4; i++) cf[mt][nt][i] = 0.f;

#pragma unroll
        for (int kki = 0; kki < 6; kki++) {
            uint32_t a[2][4];
#pragma unroll
            for (int mt = 0; mt < 2; mt++) {
                uint4 av = *(const uint4*)(QPp + (((wm * 2 + mt) * 6 + kki) * 32 + lane) * 16);
                a[mt][0] = av.x; a[mt][1] = av.y; a[mt][2] = av.z; a[mt][3] = av.w;
            }
#pragma unroll
            for (int nt = 0; nt < 4; nt++) {
                uint2 bv = *(const uint2*)(KPp + (((wn * 4 + nt) * 6 + kki) * 32 + lane) * 8);
#pragma unroll
                for (int mt = 0; mt < 2; mt++)
                    MMAH(cf[mt][nt], a[mt], bv.x, bv.y);
            }
        }

        // normalize -> final attn write + fp16 pe stage
#pragma unroll
        for (int mt = 0; mt < 2; mt++)
#pragma unroll
            for (int nt = 0; nt < 4; nt++) {
                int lc = wn * 32 + nt * 8 + 2 * t;
                float m0 = ms[lc], m1 = ms[lc + 1];
                int gc = c * TK + lc;
                float e00 = fexp(cf[mt][nt][0] * SCALE + m0) * inv[mt][0];
                float e01 = fexp(cf[mt][nt][1] * SCALE + m1) * inv[mt][0];
                float e10 = fexp(cf[mt][nt][2] * SCALE + m0) * inv[mt][1];
                float e11 = fexp(cf[mt][nt][3] * SCALE + m1) * inv[mt][1];
                int r0 = wm * 32 + mt * 16 + g;
                *(float2*)(Ab + (size_t)r0 * SS + gc)       = make_float2(e00, e01);
                *(float2*)(Ab + (size_t)(r0 + 8) * SS + gc) = make_float2(e10, e11);
                int G = (wm * 2 + mt) * 8 + wn * 2 + (nt >> 1);
                int kh = nt & 1;
                *(uint2*)(PEp + (G * 32 + lane) * 16 + kh * 8) =
                    make_uint2(ph2(e00, e01), ph2(e10, e11));
            }
        __syncthreads();

        // prefetch K(c+1) (overlaps PV)
        if (c + 1 < NCH) {
            const __half* Kn = Kb + (size_t)(c + 1) * 12288;
#pragma unroll
            for (int l = 0; l < 6; l++) {
                int i = tid + l * 256;
                cp16(kpb + (uint32_t)i * 16, Kn + i * 8);
            }
            asm volatile("cp.async.commit_group;" ::: "memory");
        }

        // PV: a from fp16 pe (LDS.128), b from permuted gmem V (LDG.64)
        const __half* Vc = Vb + (size_t)c * 12288;
#pragma unroll 4
        for (int kki = 0; kki < 8; kki++) {
            uint32_t a[2][4];
#pragma unroll
            for (int mt = 0; mt < 2; mt++) {
                uint4 av = *(const uint4*)(PEp + (((wm * 2 + mt) * 8 + kki) * 32 + lane) * 16);
                a[mt][0] = av.x; a[mt][1] = av.y; a[mt][2] = av.z; a[mt][3] = av.w;
            }
#pragma unroll
            for (int nt = 0; nt < 3; nt++) {
                uint2 bv = __ldg((const uint2*)(Vc + ((kki * 12 + wn * 3 + nt) * 32 + lane) * 4));
#pragma unroll
                for (int mt = 0; mt < 2; mt++)
                    MMAH(cx[mt][nt], a[mt], bv.x, bv.y);
            }
        }
        __syncthreads();
    }

    // ctx write: fp16 A-frag permuted (proj_out consumes directly)
#pragma unroll
    for (int mt = 0; mt < 2; mt++)
#pragma unroll
        for (int nt = 0; nt < 3; nt++) {
            int col = h * DH + wn * 24 + nt * 8 + 2 * t;
            int kki = col >> 4, kh = (col >> 3) & 1;
            int row0 = b * SS + qt * QT + wm * 32 + mt * 16 + g;
            int mtg = row0 >> 4;
            __half* dst = ctxp + ((size_t)(mtg * 48 + kki) * 32 + lane) * 8 + kh * 4;
            *(uint2*)dst = make_uint2(ph2(cx[mt][nt][0], cx[mt][nt][1]),
                                      ph2(cx[mt][nt][2], cx[mt][nt][3]));
        }
}

// ---------------- launch ----------------------------------------------------
static void* symaddr(const void* sym) {
    void* p = 0;
    cudaGetSymbolAddress(&p, sym);
    return p;
}

extern "C" void kernel_launch(void* const* d_in, const int* in_sizes, int n_in,
                              void* d_out, int out_size)
{
    const float* q_in = (const float*)d_in[0];
    const float* k_in = (const float*)d_in[1];
    const float* v_in = (const float*)d_in[2];
    const float* mask = (const float*)d_in[3];
    const float* wq = (const float*)d_in[4];
    const float* bq = (const float*)d_in[5];
    const float* wk = (const float*)d_in[6];
    const float* bk = (const float*)d_in[7];
    const float* wv = (const float*)d_in[8];
    const float* bv = (const float*)d_in[9];
    const float* wo = (const float*)d_in[10];
    const float* bo = (const float*)d_in[11];

    __half* pXp  = (__half*)symaddr(g_Xp);
    __half* pQ   = (__half*)symaddr(g_Qp);
    __half* pK   = (__half*)symaddr(g_Kp);
    __half* pV   = (__half*)symaddr(g_Vp);
    __half* pctx = (__half*)symaddr(g_ctxp);
    __half* pWp  = (__half*)symaddr(g_Wp);

    const long long OUT_E = (long long)ROWS * DM;
    const long long ATT_E = (long long)BB * HH * SS * (long long)SS;

    float* outp  = (float*)d_out;
    float* attnp;
    if ((long long)out_size >= OUT_E + ATT_E) {
        attnp = (float*)d_out + OUT_E;
    } else if ((long long)out_size == ATT_E) {
        attnp = (float*)d_out;
        outp  = (float*)symaddr(g_out_fb);
    } else {
        attnp = (float*)symaddr(g_attn_fb);
    }

    static bool attr_done = false;
    if (!attr_done) {
        cudaFuncSetAttribute(attn_kernel, cudaFuncAttributeMaxDynamicSharedMemorySize, ATTN_SMEM);
        attr_done = true;
    }

    // 1) weights -> fp16 B-frag permuted
    wt4_kernel<<<dim3(DM / 32, DM / 32, 4), dim3(32, 8)>>>(wq, wk, wv, wo, pWp);

    // 2) inputs -> fp16 A-frag permuted
    xcvt_kernel<<<dim3(ROWS * (DM / 2) / 256, 3), 256>>>(q_in, k_in, v_in, pXp);

    // 3) fused Q/K/V projections (fp16 mma); epilogues emit permuted fp16 Q/K/V
    proj_qkv<<<dim3(DM / 128, ROWS / 128, 3), 256>>>(pXp, bq, bk, bv, pWp, pQ, pK, pV);

    // 4) attention (fp16 frags; recompute-QK; fp32 attn out; fp16 permuted ctx)
    attn_kernel<<<dim3(SS / QT, HH, BB), 256, ATTN_SMEM>>>(pQ, pK, pV, mask, attnp, pctx);

    // 5) output projection (consumes permuted fp16 ctx, fp32 out)
    proj_out<<<dim3(DM / 128, ROWS / 128), 256>>>(pctx, pWp + 3 * (size_t)DM * DM, bo, outp);
}